// round 9
// baseline (speedup 1.0000x reference)
#include <cuda_runtime.h>
#include <cuda_bf16.h>
#include <cuda_pipeline.h>
#include <mma.h>
#include <cstdint>
#include <cstddef>
#include <math.h>

using namespace nvcuda;

#define S_LEN 128
#define BATCH 16
#define HID   1024
#define G4    4096
#define ROWS  2048            // S*B
#define VOC   32000
#define WS_LD 1032            // padded smem leading dim (lstm)
#define PASS_SMEM_BYTES (48 * WS_LD * 4)                      // 198144
#define GM_LD 36              // gemm smem row pad (floats)
#define GM_STAGE_FLOATS ((128 + 256) * GM_LD)                 // 13824
#define GEMM_SMEM_BYTES (2 * GM_STAGE_FLOATS * 4)             // 110592

// ---------------- static device scratch (no cudaMalloc anywhere) -------------
__device__ __align__(16) float d_X [ROWS*HID];
__device__ __align__(16) float d_G0[ROWS*G4];
__device__ __align__(16) float d_G1[ROWS*G4];
__device__ __align__(16) float d_Y0[ROWS*HID];
__device__ __align__(16) float d_D0[ROWS*HID];
__device__ __align__(16) float d_D1[ROWS*HID];
__device__ __align__(16) float d_hbuf[2][BATCH*HID];
__device__ __align__(16) float d_he0[BATCH*HID];
__device__ __align__(16) float d_ce0[BATCH*HID];
__device__ __align__(16) float d_he1[BATCH*HID];
__device__ __align__(16) float d_ce1[BATCH*HID];
__device__ __align__(16) float d_dh0[BATCH*HID];
__device__ __align__(16) float d_dh1[BATCH*HID];
__device__ __align__(16) float d_zeros[BATCH*HID];
__device__ __align__(16) float d_bc0[G4];
__device__ __align__(16) float d_bc1[G4];
__device__ int d_done[4];

__device__ __forceinline__ float sigf(float x) { return 1.0f / (1.0f + expf(-x)); }

// ---------------- init: reset counters, combine biases, zero state -----------
__global__ void init_kernel(const float* __restrict__ bih0, const float* __restrict__ bhh0,
                            const float* __restrict__ bih1, const float* __restrict__ bhh1) {
    int tid = blockIdx.x * blockDim.x + threadIdx.x;   // 4096 threads
    if (tid < 4) d_done[tid] = 0;
    for (int i = tid; i < BATCH*HID; i += 4096) d_zeros[i] = 0.0f;
    if (tid < G4) {
        d_bc0[tid] = bih0[tid] + bhh0[tid];
        d_bc1[tid] = bih1[tid] + bhh1[tid];
    }
}

// ---------------- embedding gather -------------------------------------------
__global__ void embed_kernel(const int* __restrict__ tokens, const float* __restrict__ emb) {
    int row = blockIdx.x;                              // t*B + b
    int tok = tokens[row];
    const float4* src = (const float4*)(emb + (size_t)tok * HID);
    float4* dst = (float4*)(d_X + (size_t)row * HID);
    for (int i = threadIdx.x; i < HID/4; i += blockDim.x) dst[i] = src[i];
}

// ---------------- tf32 WMMA GEMM: CTA 128x256, warp 64x64, 2-stage cp.async --
// C[M,N] = A[M,K] @ B[N,K]^T + bias[N];  grid=(M/128, N/256), block=256
__global__ void __launch_bounds__(256) gemm_tf32_bias(
    const float* __restrict__ A, const float* __restrict__ B,
    const float* __restrict__ bias, float* __restrict__ C, int N, int K)
{
    extern __shared__ float smg[];
    const int tid = threadIdx.x;
    const int m0 = blockIdx.x * 128;
    const int n0 = blockIdx.y * 256;
    const int w  = tid >> 5;
    const int lane = tid & 31;
    const int wm = w & 1;            // 2 warps along M
    const int wn = w >> 1;           // 4 warps along N

    wmma::fragment<wmma::accumulator, 16, 16, 8, float> acc[4][4];
#pragma unroll
    for (int mi = 0; mi < 4; mi++)
#pragma unroll
        for (int nj = 0; nj < 4; nj++) wmma::fill_fragment(acc[mi][nj], 0.0f);

    const int NT = K / 32;

    auto load_stage = [&](int s, int k0) {
        float* As = smg + s * GM_STAGE_FLOATS;
        float* Bs = As + 128 * GM_LD;
#pragma unroll
        for (int j = 0; j < 4; j++) {
            int idx = tid + j * 256;           // 0..1023
            int row = idx >> 3, c4 = idx & 7;
            __pipeline_memcpy_async(As + row * GM_LD + c4 * 4,
                                    A + (size_t)(m0 + row) * K + k0 + c4 * 4, 16);
        }
#pragma unroll
        for (int j = 0; j < 8; j++) {
            int idx = tid + j * 256;           // 0..2047
            int row = idx >> 3, c4 = idx & 7;
            __pipeline_memcpy_async(Bs + row * GM_LD + c4 * 4,
                                    B + (size_t)(n0 + row) * K + k0 + c4 * 4, 16);
        }
        __pipeline_commit();
    };

    load_stage(0, 0);

    for (int kt = 0; kt < NT; kt++) {
        if (kt + 1 < NT) {
            load_stage((kt + 1) & 1, (kt + 1) * 32);
            __pipeline_wait_prior(1);
        } else {
            __pipeline_wait_prior(0);
        }
        __syncthreads();
        float* As = smg + (kt & 1) * GM_STAGE_FLOATS;
        float* Bs = As + 128 * GM_LD;
#pragma unroll
        for (int kk = 0; kk < 32; kk += 8) {
            wmma::fragment<wmma::matrix_a, 16, 16, 8, wmma::precision::tf32, wmma::row_major> fa[4];
            wmma::fragment<wmma::matrix_b, 16, 16, 8, wmma::precision::tf32, wmma::col_major> fb[4];
#pragma unroll
            for (int mi = 0; mi < 4; mi++) {
                wmma::load_matrix_sync(fa[mi], As + (wm * 64 + mi * 16) * GM_LD + kk, GM_LD);
#pragma unroll
                for (int e = 0; e < fa[mi].num_elements; e++)
                    fa[mi].x[e] = wmma::__float_to_tf32(fa[mi].x[e]);
            }
#pragma unroll
            for (int nj = 0; nj < 4; nj++) {
                wmma::load_matrix_sync(fb[nj], Bs + (wn * 64 + nj * 16) * GM_LD + kk, GM_LD);
#pragma unroll
                for (int e = 0; e < fb[nj].num_elements; e++)
                    fb[nj].x[e] = wmma::__float_to_tf32(fb[nj].x[e]);
            }
#pragma unroll
            for (int mi = 0; mi < 4; mi++)
#pragma unroll
                for (int nj = 0; nj < 4; nj++)
                    wmma::mma_sync(acc[mi][nj], fa[mi], fb[nj], acc[mi][nj]);
        }
        __syncthreads();
    }
    __syncthreads();   // all mma done before epilogue overlays stage smem

    // epilogue: per-warp private 16x64 slab, bias add, coalesced global stores
    float* slab = smg + w * 1024;
#pragma unroll
    for (int mi = 0; mi < 4; mi++) {
#pragma unroll
        for (int nj = 0; nj < 4; nj++)
            wmma::store_matrix_sync(slab + nj * 16, acc[mi][nj], 64, wmma::mem_row_major);
        __syncwarp();
#pragma unroll 4
        for (int i = 0; i < 32; i++) {
            int idx = i * 32 + lane;       // 0..1023
            int r = idx >> 6;              // 0..15
            int c = idx & 63;              // 0..63
            float v = slab[r * 64 + c] + __ldg(&bias[n0 + wn * 64 + c]);
            C[(size_t)(m0 + wm * 64 + mi * 16 + r) * N + n0 + wn * 64 + c] = v;
        }
        __syncwarp();
    }
}

// ---------------- persistent LSTM layer pass ---------------------------------
// 128 CTAs, 1/SM, co-resident (198KB smem). CTA n owns hidden units [8n,8n+8)
// and all 4 gates for them. Whh fragments PRELOADED INTO REGISTERS (16 warps,
// K slice 64 each, 64 regs of weights/thread); weight smem reused as reduce buf.
__global__ void __launch_bounds__(512, 1) lstm_pass(
    const float* __restrict__ Gpre, const float* __restrict__ Whh,
    const float* __restrict__ h0, const float* __restrict__ c0,
    float* __restrict__ y, float* __restrict__ hout, float* __restrict__ cout, int pass)
{
    extern __shared__ float sm[];
    float* ws  = sm;                       // [32][WS_LD] weights (init only)
    float* hs  = sm + 32 * WS_LD;          // [16][WS_LD] h staging
    float* red = sm;                       // overlay after preload: 16 x [16][36]
    const int tid = threadIdx.x;
    const int cta = blockIdx.x;
    const int w   = tid >> 5;              // 0..15

    // stage weights to smem once (tf32-rounded)
    for (int i = tid; i < 32 * 256; i += 512) {
        int r = i >> 8, c = i & 255;
        int grow = (r >> 3) * HID + cta * 8 + (r & 7);
        float4 v = __ldg((const float4*)(Whh + (size_t)grow * HID) + c);
        v.x = wmma::__float_to_tf32(v.x); v.y = wmma::__float_to_tf32(v.y);
        v.z = wmma::__float_to_tf32(v.z); v.w = wmma::__float_to_tf32(v.w);
        ((float4*)(ws + r * WS_LD))[c] = v;
    }
    __syncthreads();

    // preload this warp's weight fragments into registers (K slice [64w,64w+64))
    wmma::fragment<wmma::matrix_b, 16, 16, 8, wmma::precision::tf32, wmma::col_major> fw[8][2];
#pragma unroll
    for (int kk = 0; kk < 8; kk++) {
        int k = w * 64 + kk * 8;
        wmma::load_matrix_sync(fw[kk][0], ws + k, WS_LD);
        wmma::load_matrix_sync(fw[kk][1], ws + 16 * WS_LD + k, WS_LD);
    }
    __syncthreads();                       // ws now dead; red overlay is safe

    volatile int* vd = (volatile int*)&d_done[pass];
    const int b  = tid >> 3;               // valid for tid<128
    const int du = tid & 7;
    const int j  = cta * 8 + du;
    float creg = 0.0f;
    if (tid < 128) creg = c0[b * HID + j];

#pragma unroll 1
    for (int t = 0; t < S_LEN; t++) {
        // prefetch input-projection gates (independent of h) before the spin
        float gp0 = 0.f, gp1 = 0.f, gp2 = 0.f, gp3 = 0.f;
        if (tid < 128) {
            const float* g = Gpre + (size_t)t * BATCH * G4 + b * G4 + j;
            gp0 = __ldg(g); gp1 = __ldg(g + HID); gp2 = __ldg(g + 2*HID); gp3 = __ldg(g + 3*HID);
        }
        if (t > 0) { if (tid == 0) { while (*vd < 128 * t) { } } }
        __syncthreads();

        // stage h[t-1] (L2-coherent reads), round to tf32
        {
            const float4* src = (t == 0) ? (const float4*)h0
                                         : (const float4*)d_hbuf[(t + 1) & 1];
#pragma unroll
            for (int q = 0; q < 8; q++) {
                int i = tid + q * 512;         // 0..4095
                float4 v = __ldcg(src + i);
                v.x = wmma::__float_to_tf32(v.x); v.y = wmma::__float_to_tf32(v.y);
                v.z = wmma::__float_to_tf32(v.z); v.w = wmma::__float_to_tf32(v.w);
                ((float4*)(hs + (i >> 8) * WS_LD))[i & 255] = v;
            }
        }
        __syncthreads();

        // 16x32x1024 matmul, K split across 16 warps, weights in registers
        {
            wmma::fragment<wmma::accumulator, 16, 16, 8, float> a0, a1;
            wmma::fill_fragment(a0, 0.0f);
            wmma::fill_fragment(a1, 0.0f);
#pragma unroll
            for (int kk = 0; kk < 8; kk++) {
                wmma::fragment<wmma::matrix_a, 16, 16, 8, wmma::precision::tf32, wmma::row_major> fa;
                wmma::load_matrix_sync(fa, hs + w * 64 + kk * 8, WS_LD);
                wmma::mma_sync(a0, fa, fw[kk][0], a0);
                wmma::mma_sync(a1, fa, fw[kk][1], a1);
            }
            wmma::store_matrix_sync(red + w * 576,      a0, 36, wmma::mem_row_major);
            wmma::store_matrix_sync(red + w * 576 + 16, a1, 36, wmma::mem_row_major);
        }
        __syncthreads();

        // reduce 16 partials, apply LSTM elementwise (CTA owns all 4 gates)
        float hv = 0.f, cv = 0.f;
        if (tid < 128) {
            float s0 = gp0, s1 = gp1, s2 = gp2, s3 = gp3;
#pragma unroll
            for (int p = 0; p < 16; p++) {
                const float* rp = red + p * 576 + b * 36;
                s0 += rp[du]; s1 += rp[8 + du]; s2 += rp[16 + du]; s3 += rp[24 + du];
            }
            cv = sigf(s1) * creg + sigf(s0) * tanhf(s2);
            hv = sigf(s3) * tanhf(cv);
            creg = cv;
            d_hbuf[t & 1][b * HID + j] = hv;
        }
        __threadfence();
        __syncthreads();
        if (tid == 0) atomicAdd(&d_done[pass], 1);
        // off-critical-path stores (consumed only after this kernel finishes)
        if (tid < 128) {
            y[(size_t)t * BATCH * HID + b * HID + j] = hv;
            if (t == S_LEN - 1) { hout[b * HID + j] = hv; cout[b * HID + j] = cv; }
        }
    }
}

// ---------------- latent linear: dh = he @ latW^T + latb (fp32 exact) --------
__global__ void latent_kernel(const float* __restrict__ latW, const float* __restrict__ latb) {
    __shared__ float hesh[HID];
    int blk = blockIdx.x;
    int which = blk >> 10;
    int rem = blk & 1023;
    int b = rem >> 6;
    int jg = rem & 63;
    const float* he = which ? d_he1 : d_he0;
    float* dh = which ? d_dh1 : d_dh0;
    for (int i = threadIdx.x; i < HID; i += 256) hesh[i] = he[b * HID + i];
    __syncthreads();
    int w = threadIdx.x >> 5, lane = threadIdx.x & 31;
#pragma unroll
    for (int q = 0; q < 2; q++) {
        int j = jg * 16 + w * 2 + q;
        const float* wr = latW + (size_t)j * HID;
        float s = 0.0f;
        for (int k = lane; k < HID; k += 32) s += wr[k] * hesh[k];
#pragma unroll
        for (int o = 16; o; o >>= 1) s += __shfl_xor_sync(0xFFFFFFFFu, s, o);
        if (lane == 0) dh[b * HID + j] = s + latb[j];
    }
}

// ---------------- host orchestration -----------------------------------------
extern "C" void kernel_launch(void* const* d_in, const int* in_sizes, int n_in,
                              void* d_out, int out_size) {
    const int*   tokens   = (const int*)  d_in[0];
    const float* emb      = (const float*)d_in[1];
    const float* dec_bias = (const float*)d_in[2];
    const float* Wih0     = (const float*)d_in[3];
    const float* Whh0     = (const float*)d_in[4];
    const float* bih0     = (const float*)d_in[5];
    const float* bhh0     = (const float*)d_in[6];
    const float* Wih1     = (const float*)d_in[7];
    const float* Whh1     = (const float*)d_in[8];
    const float* bih1     = (const float*)d_in[9];
    const float* bhh1     = (const float*)d_in[10];
    const float* latW     = (const float*)d_in[11];
    const float* latb     = (const float*)d_in[12];
    float* out = (float*)d_out;

    cudaFuncSetAttribute(gemm_tf32_bias, cudaFuncAttributeMaxDynamicSharedMemorySize, GEMM_SMEM_BYTES);
    cudaFuncSetAttribute(lstm_pass,      cudaFuncAttributeMaxDynamicSharedMemorySize, PASS_SMEM_BYTES);

    float *pX, *pG0, *pG1, *pY0, *pD0, *pD1, *pZ, *pbc0, *pbc1;
    float *phe0, *pce0, *phe1, *pce1, *pdh0, *pdh1;
    cudaGetSymbolAddress((void**)&pX,   d_X);
    cudaGetSymbolAddress((void**)&pG0,  d_G0);
    cudaGetSymbolAddress((void**)&pG1,  d_G1);
    cudaGetSymbolAddress((void**)&pY0,  d_Y0);
    cudaGetSymbolAddress((void**)&pD0,  d_D0);
    cudaGetSymbolAddress((void**)&pD1,  d_D1);
    cudaGetSymbolAddress((void**)&pZ,   d_zeros);
    cudaGetSymbolAddress((void**)&pbc0, d_bc0);
    cudaGetSymbolAddress((void**)&pbc1, d_bc1);
    cudaGetSymbolAddress((void**)&phe0, d_he0);
    cudaGetSymbolAddress((void**)&pce0, d_ce0);
    cudaGetSymbolAddress((void**)&phe1, d_he1);
    cudaGetSymbolAddress((void**)&pce1, d_ce1);
    cudaGetSymbolAddress((void**)&pdh0, d_dh0);
    cudaGetSymbolAddress((void**)&pdh1, d_dh1);

    init_kernel<<<16, 256>>>(bih0, bhh0, bih1, bhh1);
    embed_kernel<<<ROWS, 256>>>(tokens, emb);

    // G0 = X @ Wih0^T + (bih0+bhh0)  (shared by enc-l0 and teacher-forced dec-l0)
    gemm_tf32_bias<<<dim3(16, 16), 256, GEMM_SMEM_BYTES>>>(pX, Wih0, pbc0, pG0, G4, HID);
    lstm_pass<<<128, 512, PASS_SMEM_BYTES>>>(pG0, Whh0, pZ, pZ, pY0, phe0, pce0, 0);
    gemm_tf32_bias<<<dim3(16, 16), 256, GEMM_SMEM_BYTES>>>(pY0, Wih1, pbc1, pG1, G4, HID);
    lstm_pass<<<128, 512, PASS_SMEM_BYTES>>>(pG1, Whh1, pZ, pZ, pD1, phe1, pce1, 1);
    latent_kernel<<<2048, 256>>>(latW, latb);
    lstm_pass<<<128, 512, PASS_SMEM_BYTES>>>(pG0, Whh0, pdh0, pce0, pD0, phe0, pce0, 2);
    gemm_tf32_bias<<<dim3(16, 16), 256, GEMM_SMEM_BYTES>>>(pD0, Wih1, pbc1, pG1, G4, HID);
    lstm_pass<<<128, 512, PASS_SMEM_BYTES>>>(pG1, Whh1, pdh1, pce1, pD1, phe1, pce1, 3);
    // logits = D1 @ emb^T + dec_bias   [2048, 32000]
    gemm_tf32_bias<<<dim3(16, 125), 256, GEMM_SMEM_BYTES>>>(pD1, emb, dec_bias, out, VOC, HID);
}

// round 12
// speedup vs baseline: 2.1973x; 2.1973x over previous
#include <cuda_runtime.h>
#include <cuda_fp16.h>
#include <cuda_pipeline.h>
#include <mma.h>
#include <cstdint>
#include <cstddef>
#include <math.h>

using namespace nvcuda;

#define S_LEN 128
#define BATCH 16
#define HID   1024
#define G4    4096
#define ROWS  2048            // S*B
#define VOC   32000
#define WS_LD 1032            // padded smem leading dim (lstm)
#define PASS_SMEM_BYTES ((32*WS_LD + 16*WS_LD + 8*576) * 4)   // 216576
#define GH_LD 72              // gemm smem row pad (halves): 64 data + 8 pad
#define GH_STAGE_HALVES ((128 + 256) * GH_LD)                 // 27648
#define GEMM_SMEM_BYTES (2 * GH_STAGE_HALVES * 2)             // 110592

// ---------------- static device scratch (no cudaMalloc anywhere) -------------
__device__ __align__(16) __half d_embH[VOC*HID];    // fp16 emb (GEMM operand)
__device__ __align__(16) __half d_WH0[G4*HID];      // fp16 Wih0
__device__ __align__(16) __half d_WH1[G4*HID];      // fp16 Wih1
__device__ __align__(16) __half d_X [ROWS*HID];     // fp16 embedded input
__device__ __align__(16) __half d_Y0[ROWS*HID];     // fp16 enc-l0 output
__device__ __align__(16) __half d_D0[ROWS*HID];     // fp16 dec-l0 output
__device__ __align__(16) __half d_D1[ROWS*HID];     // fp16 dec-l1 output
__device__ __align__(16) float d_G0[ROWS*G4];
__device__ __align__(16) float d_G1[ROWS*G4];
__device__ __align__(16) float d_hbuf[2][BATCH*HID];
__device__ __align__(16) float d_he0[BATCH*HID];
__device__ __align__(16) float d_ce0[BATCH*HID];
__device__ __align__(16) float d_he1[BATCH*HID];
__device__ __align__(16) float d_ce1[BATCH*HID];
__device__ __align__(16) float d_dh0[BATCH*HID];
__device__ __align__(16) float d_dh1[BATCH*HID];
__device__ __align__(16) float d_zeros[BATCH*HID];
__device__ __align__(16) float d_bc0[G4];
__device__ __align__(16) float d_bc1[G4];
__device__ int d_done[4];

__device__ __forceinline__ float sigf(float x) { return 1.0f / (1.0f + expf(-x)); }

// ---------------- init: reset counters, combine biases, zero state -----------
__global__ void init_kernel(const float* __restrict__ bih0, const float* __restrict__ bhh0,
                            const float* __restrict__ bih1, const float* __restrict__ bhh1) {
    int tid = blockIdx.x * blockDim.x + threadIdx.x;   // 4096 threads
    if (tid < 4) d_done[tid] = 0;
    for (int i = tid; i < BATCH*HID; i += 4096) d_zeros[i] = 0.0f;
    if (tid < G4) {
        d_bc0[tid] = bih0[tid] + bhh0[tid];
        d_bc1[tid] = bih1[tid] + bhh1[tid];
    }
}

// ---------------- fp32 -> fp16 convert (vectorized) --------------------------
__global__ void tohalf_kernel(const float* __restrict__ src, __half* __restrict__ dst, int n4) {
    int i = blockIdx.x * blockDim.x + threadIdx.x;
    if (i < n4) {
        float4 v = ((const float4*)src)[i];
        __half2 a = __floats2half2_rn(v.x, v.y);
        __half2 b = __floats2half2_rn(v.z, v.w);
        ((__half2*)dst)[2*i]   = a;
        ((__half2*)dst)[2*i+1] = b;
    }
}

// ---------------- embedding gather (fp16 rows) -------------------------------
__global__ void embed_kernel(const int* __restrict__ tokens) {
    int row = blockIdx.x;                              // t*B + b
    int tok = tokens[row];
    const uint4* src = (const uint4*)(d_embH + (size_t)tok * HID);
    uint4* dst = (uint4*)(d_X + (size_t)row * HID);
    for (int i = threadIdx.x; i < HID/8; i += blockDim.x) dst[i] = src[i];
}

// ---------------- fp16 WMMA GEMM: CTA 128x256, warp 64x64, 2-stage cp.async --
// C[M,N] = A[M,K] @ B[N,K]^T + bias[N];  grid=(M/128, N/256), block=256
// Operands fp16 in gmem (same mantissa as tf32); fp32 accumulate + bias.
__global__ void __launch_bounds__(256) gemm_h(
    const __half* __restrict__ A, const __half* __restrict__ B,
    const float* __restrict__ bias, float* __restrict__ C, int N, int K)
{
    extern __shared__ __half smh[];
    const int tid = threadIdx.x;
    const int m0 = blockIdx.x * 128;
    const int n0 = blockIdx.y * 256;
    const int w  = tid >> 5;
    const int lane = tid & 31;
    const int wm = w & 1;            // 2 warps along M
    const int wn = w >> 1;           // 4 warps along N

    wmma::fragment<wmma::accumulator, 16, 16, 16, float> acc[4][4];
#pragma unroll
    for (int mi = 0; mi < 4; mi++)
#pragma unroll
        for (int nj = 0; nj < 4; nj++) wmma::fill_fragment(acc[mi][nj], 0.0f);

    const int NT = K / 64;           // 16 k-tiles of 64 halves

    auto load_stage = [&](int s, int k0) {
        __half* As = smh + s * GH_STAGE_HALVES;
        __half* Bs = As + 128 * GH_LD;
        // A: 128 rows x 64 halves = 1024 x 16B chunks
#pragma unroll
        for (int j = 0; j < 4; j++) {
            int idx = tid + j * 256;           // 0..1023
            int row = idx >> 3, c8 = idx & 7;
            __pipeline_memcpy_async(As + row * GH_LD + c8 * 8,
                                    A + (size_t)(m0 + row) * K + k0 + c8 * 8, 16);
        }
        // B: 256 rows x 64 halves = 2048 chunks
#pragma unroll
        for (int j = 0; j < 8; j++) {
            int idx = tid + j * 256;           // 0..2047
            int row = idx >> 3, c8 = idx & 7;
            __pipeline_memcpy_async(Bs + row * GH_LD + c8 * 8,
                                    B + (size_t)(n0 + row) * K + k0 + c8 * 8, 16);
        }
        __pipeline_commit();
    };

    load_stage(0, 0);

    for (int kt = 0; kt < NT; kt++) {
        if (kt + 1 < NT) {
            load_stage((kt + 1) & 1, (kt + 1) * 64);
            __pipeline_wait_prior(1);
        } else {
            __pipeline_wait_prior(0);
        }
        __syncthreads();
        __half* As = smh + (kt & 1) * GH_STAGE_HALVES;
        __half* Bs = As + 128 * GH_LD;
#pragma unroll
        for (int kk = 0; kk < 64; kk += 16) {
            wmma::fragment<wmma::matrix_a, 16, 16, 16, __half, wmma::row_major> fa[4];
            wmma::fragment<wmma::matrix_b, 16, 16, 16, __half, wmma::col_major> fb[4];
#pragma unroll
            for (int mi = 0; mi < 4; mi++)
                wmma::load_matrix_sync(fa[mi], As + (wm * 64 + mi * 16) * GH_LD + kk, GH_LD);
#pragma unroll
            for (int nj = 0; nj < 4; nj++)
                wmma::load_matrix_sync(fb[nj], Bs + (wn * 64 + nj * 16) * GH_LD + kk, GH_LD);
#pragma unroll
            for (int mi = 0; mi < 4; mi++)
#pragma unroll
                for (int nj = 0; nj < 4; nj++)
                    wmma::mma_sync(acc[mi][nj], fa[mi], fb[nj], acc[mi][nj]);
        }
        __syncthreads();
    }
    __syncthreads();   // all mma done before epilogue overlays stage smem

    // epilogue: per-warp private 16x64 fp32 slab, bias add, coalesced stores
    float* slab = ((float*)smh) + w * 1024;
#pragma unroll
    for (int mi = 0; mi < 4; mi++) {
#pragma unroll
        for (int nj = 0; nj < 4; nj++)
            wmma::store_matrix_sync(slab + nj * 16, acc[mi][nj], 64, wmma::mem_row_major);
        __syncwarp();
#pragma unroll 4
        for (int i = 0; i < 32; i++) {
            int idx = i * 32 + lane;       // 0..1023
            int r = idx >> 6;              // 0..15
            int c = idx & 63;              // 0..63
            float v = slab[r * 64 + c] + __ldg(&bias[n0 + wn * 64 + c]);
            C[(size_t)(m0 + wm * 64 + mi * 16 + r) * N + n0 + wn * 64 + c] = v;
        }
        __syncwarp();
    }
}

// ---------------- persistent LSTM layer pass (exact R6 structure) ------------
// 128 CTAs, 1/SM, co-resident. CTA n owns hidden units [8n,8n+8) and all 4
// gates (32 Whh rows resident in smem). Cell state in registers; h broadcast
// via L2 double buffer. y output stored as fp16 (GEMM operand only).
__global__ void __launch_bounds__(256, 1) lstm_pass(
    const float* __restrict__ Gpre, const float* __restrict__ Whh,
    const float* __restrict__ h0, const float* __restrict__ c0,
    __half* __restrict__ y, float* __restrict__ hout, float* __restrict__ cout, int pass)
{
    extern __shared__ float sm[];
    float* ws  = sm;                       // [32][WS_LD] weights (tf32-rounded)
    float* hs  = sm + 32 * WS_LD;          // [16][WS_LD] h staging
    float* red = sm + 48 * WS_LD;          // 8 warps x [16][36]
    const int tid = threadIdx.x;
    const int cta = blockIdx.x;
    const int w   = tid >> 5;

    for (int i = tid; i < 32 * 256; i += 256) {
        int r = i >> 8, c = i & 255;
        int grow = (r >> 3) * HID + cta * 8 + (r & 7);
        float4 v = __ldg((const float4*)(Whh + (size_t)grow * HID) + c);
        v.x = wmma::__float_to_tf32(v.x); v.y = wmma::__float_to_tf32(v.y);
        v.z = wmma::__float_to_tf32(v.z); v.w = wmma::__float_to_tf32(v.w);
        ((float4*)(ws + r * WS_LD))[c] = v;
    }
    __syncthreads();

    volatile int* vd = (volatile int*)&d_done[pass];
    const int b  = tid >> 3;               // valid for tid<128
    const int du = tid & 7;
    const int j  = cta * 8 + du;
    float creg = 0.0f;
    if (tid < 128) creg = c0[b * HID + j];

#pragma unroll 1
    for (int t = 0; t < S_LEN; t++) {
        float gp0 = 0.f, gp1 = 0.f, gp2 = 0.f, gp3 = 0.f;
        if (tid < 128) {
            const float* g = Gpre + (size_t)t * BATCH * G4 + b * G4 + j;
            gp0 = __ldg(g); gp1 = __ldg(g + HID); gp2 = __ldg(g + 2*HID); gp3 = __ldg(g + 3*HID);
        }
        if (t > 0) { if (tid == 0) { while (*vd < 128 * t) { } } }
        __syncthreads();

        {
            const float4* src = (t == 0) ? (const float4*)h0
                                         : (const float4*)d_hbuf[(t + 1) & 1];
#pragma unroll
            for (int q = 0; q < 16; q++) {
                int i = tid + q * 256;         // 0..4095
                float4 v = __ldcg(src + i);
                v.x = wmma::__float_to_tf32(v.x); v.y = wmma::__float_to_tf32(v.y);
                v.z = wmma::__float_to_tf32(v.z); v.w = wmma::__float_to_tf32(v.w);
                ((float4*)(hs + (i >> 8) * WS_LD))[i & 255] = v;
            }
        }
        __syncthreads();

        {
            wmma::fragment<wmma::accumulator, 16, 16, 8, float> a0, a1;
            wmma::fill_fragment(a0, 0.0f);
            wmma::fill_fragment(a1, 0.0f);
#pragma unroll
            for (int kk = 0; kk < 128; kk += 8) {
                int k = w * 128 + kk;
                wmma::fragment<wmma::matrix_a, 16, 16, 8, wmma::precision::tf32, wmma::row_major> fa;
                wmma::fragment<wmma::matrix_b, 16, 16, 8, wmma::precision::tf32, wmma::col_major> f0, f1;
                wmma::load_matrix_sync(fa, hs + k, WS_LD);
                wmma::load_matrix_sync(f0, ws + k, WS_LD);
                wmma::load_matrix_sync(f1, ws + 16 * WS_LD + k, WS_LD);
                wmma::mma_sync(a0, fa, f0, a0);
                wmma::mma_sync(a1, fa, f1, a1);
            }
            wmma::store_matrix_sync(red + w * 576,      a0, 36, wmma::mem_row_major);
            wmma::store_matrix_sync(red + w * 576 + 16, a1, 36, wmma::mem_row_major);
        }
        __syncthreads();

        if (tid < 128) {
            float s0 = gp0, s1 = gp1, s2 = gp2, s3 = gp3;
#pragma unroll
            for (int p = 0; p < 8; p++) {
                const float* rp = red + p * 576 + b * 36;
                s0 += rp[du]; s1 += rp[8 + du]; s2 += rp[16 + du]; s3 += rp[24 + du];
            }
            float c = sigf(s1) * creg + sigf(s0) * tanhf(s2);
            float h = sigf(s3) * tanhf(c);
            creg = c;
            d_hbuf[t & 1][b * HID + j] = h;
            y[(size_t)t * BATCH * HID + b * HID + j] = __float2half_rn(h);
            if (t == S_LEN - 1) { hout[b * HID + j] = h; cout[b * HID + j] = c; }
        }
        __threadfence();
        __syncthreads();
        if (tid == 0) atomicAdd(&d_done[pass], 1);
    }
}

// ---------------- latent linear: dh = he @ latW^T + latb (fp32 exact) --------
__global__ void latent_kernel(const float* __restrict__ latW, const float* __restrict__ latb) {
    __shared__ float hesh[HID];
    int blk = blockIdx.x;
    int which = blk >> 10;
    int rem = blk & 1023;
    int b = rem >> 6;
    int jg = rem & 63;
    const float* he = which ? d_he1 : d_he0;
    float* dh = which ? d_dh1 : d_dh0;
    for (int i = threadIdx.x; i < HID; i += 256) hesh[i] = he[b * HID + i];
    __syncthreads();
    int w = threadIdx.x >> 5, lane = threadIdx.x & 31;
#pragma unroll
    for (int q = 0; q < 2; q++) {
        int j = jg * 16 + w * 2 + q;
        const float* wr = latW + (size_t)j * HID;
        float s = 0.0f;
        for (int k = lane; k < HID; k += 32) s += wr[k] * hesh[k];
#pragma unroll
        for (int o = 16; o; o >>= 1) s += __shfl_xor_sync(0xFFFFFFFFu, s, o);
        if (lane == 0) dh[b * HID + j] = s + latb[j];
    }
}

// ---------------- host orchestration -----------------------------------------
extern "C" void kernel_launch(void* const* d_in, const int* in_sizes, int n_in,
                              void* d_out, int out_size) {
    const int*   tokens   = (const int*)  d_in[0];
    const float* emb      = (const float*)d_in[1];
    const float* dec_bias = (const float*)d_in[2];
    const float* Wih0     = (const float*)d_in[3];
    const float* Whh0     = (const float*)d_in[4];
    const float* bih0     = (const float*)d_in[5];
    const float* bhh0     = (const float*)d_in[6];
    const float* Wih1     = (const float*)d_in[7];
    const float* Whh1     = (const float*)d_in[8];
    const float* bih1     = (const float*)d_in[9];
    const float* bhh1     = (const float*)d_in[10];
    const float* latW     = (const float*)d_in[11];
    const float* latb     = (const float*)d_in[12];
    float* out = (float*)d_out;

    cudaFuncSetAttribute(gemm_h,    cudaFuncAttributeMaxDynamicSharedMemorySize, GEMM_SMEM_BYTES);
    cudaFuncSetAttribute(lstm_pass, cudaFuncAttributeMaxDynamicSharedMemorySize, PASS_SMEM_BYTES);

    float *pG0, *pG1, *pZ, *pbc0, *pbc1;
    float *phe0, *pce0, *phe1, *pce1, *pdh0, *pdh1;
    __half *pXH, *pY0H, *pD0H, *pD1H, *pembH, *pWH0, *pWH1;
    cudaGetSymbolAddress((void**)&pG0,   d_G0);
    cudaGetSymbolAddress((void**)&pG1,   d_G1);
    cudaGetSymbolAddress((void**)&pZ,    d_zeros);
    cudaGetSymbolAddress((void**)&pbc0,  d_bc0);
    cudaGetSymbolAddress((void**)&pbc1,  d_bc1);
    cudaGetSymbolAddress((void**)&phe0,  d_he0);
    cudaGetSymbolAddress((void**)&pce0,  d_ce0);
    cudaGetSymbolAddress((void**)&phe1,  d_he1);
    cudaGetSymbolAddress((void**)&pce1,  d_ce1);
    cudaGetSymbolAddress((void**)&pdh0,  d_dh0);
    cudaGetSymbolAddress((void**)&pdh1,  d_dh1);
    cudaGetSymbolAddress((void**)&pXH,   d_X);
    cudaGetSymbolAddress((void**)&pY0H,  d_Y0);
    cudaGetSymbolAddress((void**)&pD0H,  d_D0);
    cudaGetSymbolAddress((void**)&pD1H,  d_D1);
    cudaGetSymbolAddress((void**)&pembH, d_embH);
    cudaGetSymbolAddress((void**)&pWH0,  d_WH0);
    cudaGetSymbolAddress((void**)&pWH1,  d_WH1);

    init_kernel<<<16, 256>>>(bih0, bhh0, bih1, bhh1);
    // one-time fp16 conversions of GEMM operands
    tohalf_kernel<<<(VOC*HID/4 + 255)/256, 256>>>(emb,  pembH, VOC*HID/4);
    tohalf_kernel<<<(G4*HID/4 + 255)/256, 256>>>(Wih0, pWH0,  G4*HID/4);
    tohalf_kernel<<<(G4*HID/4 + 255)/256, 256>>>(Wih1, pWH1,  G4*HID/4);
    embed_kernel<<<ROWS, 256>>>(tokens);

    // G0 = X @ Wih0^T + (bih0+bhh0)  (shared by enc-l0 and teacher-forced dec-l0)
    gemm_h<<<dim3(16, 16), 256, GEMM_SMEM_BYTES>>>(pXH, pWH0, pbc0, pG0, G4, HID);
    lstm_pass<<<128, 256, PASS_SMEM_BYTES>>>(pG0, Whh0, pZ, pZ, pY0H, phe0, pce0, 0);
    gemm_h<<<dim3(16, 16), 256, GEMM_SMEM_BYTES>>>(pY0H, pWH1, pbc1, pG1, G4, HID);
    lstm_pass<<<128, 256, PASS_SMEM_BYTES>>>(pG1, Whh1, pZ, pZ, pD1H, phe1, pce1, 1);
    latent_kernel<<<2048, 256>>>(latW, latb);
    lstm_pass<<<128, 256, PASS_SMEM_BYTES>>>(pG0, Whh0, pdh0, pce0, pD0H, phe0, pce0, 2);
    gemm_h<<<dim3(16, 16), 256, GEMM_SMEM_BYTES>>>(pD0H, pWH1, pbc1, pG1, G4, HID);
    lstm_pass<<<128, 256, PASS_SMEM_BYTES>>>(pG1, Whh1, pdh1, pce1, pD1H, phe1, pce1, 3);
    // logits = D1 @ embH^T + dec_bias   [2048, 32000]
    gemm_h<<<dim3(16, 125), 256, GEMM_SMEM_BYTES>>>(pD1H, pembH, dec_bias, out, VOC, HID);
}

// round 13
// speedup vs baseline: 3.0885x; 1.4056x over previous
#include <cuda_runtime.h>
#include <cuda_fp16.h>
#include <cuda_pipeline.h>
#include <mma.h>
#include <cstdint>
#include <cstddef>
#include <math.h>

using namespace nvcuda;

#define S_LEN 128
#define BATCH 16
#define HID   1024
#define G4    4096
#define ROWS  2048            // S*B
#define VOC   32000
#define WH_LD 1040            // lstm smem leading dim (halves): 1024 + 16
#define PASS_SMEM_BYTES ((32*WH_LD + 16*WH_LD) * 2 + 8*576*4)  // 118272
#define GH_LD 72              // gemm smem row pad (halves): 64 data + 8 pad
#define GH_STAGE_HALVES ((128 + 256) * GH_LD)                  // 27648
#define GEMM_SMEM_BYTES (2 * GH_STAGE_HALVES * 2)              // 110592

// ---------------- static device scratch (no cudaMalloc anywhere) -------------
__device__ __align__(16) __half d_embH[VOC*HID];
__device__ __align__(16) __half d_WH0[G4*HID];
__device__ __align__(16) __half d_WH1[G4*HID];
__device__ __align__(16) __half d_X [ROWS*HID];
__device__ __align__(16) __half d_Y0[ROWS*HID];
__device__ __align__(16) __half d_D0[ROWS*HID];
__device__ __align__(16) __half d_D1[ROWS*HID];
__device__ __align__(16) __half d_hbuf[2][BATCH*HID];
__device__ __align__(16) __half d_dh0H[BATCH*HID];
__device__ __align__(16) __half d_dh1H[BATCH*HID];
__device__ __align__(16) __half d_zerosH[BATCH*HID];
__device__ __align__(16) float d_zerosF[BATCH*HID];
__device__ __align__(16) float d_G0[ROWS*G4];
__device__ __align__(16) float d_G1[ROWS*G4];
__device__ __align__(16) float d_he0[BATCH*HID];
__device__ __align__(16) float d_ce0[BATCH*HID];
__device__ __align__(16) float d_he1[BATCH*HID];
__device__ __align__(16) float d_ce1[BATCH*HID];
__device__ __align__(16) float d_bc0[G4];
__device__ __align__(16) float d_bc1[G4];
__device__ int d_done[4];

__device__ __forceinline__ float sigf(float x) { return 1.0f / (1.0f + expf(-x)); }

__global__ void init_kernel(const float* __restrict__ bih0, const float* __restrict__ bhh0,
                            const float* __restrict__ bih1, const float* __restrict__ bhh1) {
    int tid = blockIdx.x * blockDim.x + threadIdx.x;   // 4096 threads
    if (tid < 4) d_done[tid] = 0;
    for (int i = tid; i < BATCH*HID; i += 4096) {
        d_zerosH[i] = __float2half(0.0f);
        d_zerosF[i] = 0.0f;
    }
    if (tid < G4) {
        d_bc0[tid] = bih0[tid] + bhh0[tid];
        d_bc1[tid] = bih1[tid] + bhh1[tid];
    }
}

__global__ void tohalf_kernel(const float* __restrict__ src, __half* __restrict__ dst, int n4) {
    int i = blockIdx.x * blockDim.x + threadIdx.x;
    if (i < n4) {
        float4 v = ((const float4*)src)[i];
        ((__half2*)dst)[2*i]   = __floats2half2_rn(v.x, v.y);
        ((__half2*)dst)[2*i+1] = __floats2half2_rn(v.z, v.w);
    }
}

__global__ void embed_kernel(const int* __restrict__ tokens) {
    int row = blockIdx.x;                              // t*B + b
    int tok = tokens[row];
    const uint4* src = (const uint4*)(d_embH + (size_t)tok * HID);
    uint4* dst = (uint4*)(d_X + (size_t)row * HID);
    for (int i = threadIdx.x; i < HID/8; i += blockDim.x) dst[i] = src[i];
}

// ---------------- fp16 WMMA GEMM: CTA 128x256, warp 64x64, 2-stage cp.async --
__global__ void __launch_bounds__(256) gemm_h(
    const __half* __restrict__ A, const __half* __restrict__ B,
    const float* __restrict__ bias, float* __restrict__ C, int N, int K)
{
    extern __shared__ __half smh[];
    const int tid = threadIdx.x;
    const int m0 = blockIdx.x * 128;
    const int n0 = blockIdx.y * 256;
    const int w  = tid >> 5;
    const int lane = tid & 31;
    const int wm = w & 1;
    const int wn = w >> 1;

    wmma::fragment<wmma::accumulator, 16, 16, 16, float> acc[4][4];
#pragma unroll
    for (int mi = 0; mi < 4; mi++)
#pragma unroll
        for (int nj = 0; nj < 4; nj++) wmma::fill_fragment(acc[mi][nj], 0.0f);

    const int NT = K / 64;

    auto load_stage = [&](int s, int k0) {
        __half* As = smh + s * GH_STAGE_HALVES;
        __half* Bs = As + 128 * GH_LD;
#pragma unroll
        for (int j = 0; j < 4; j++) {
            int idx = tid + j * 256;
            int row = idx >> 3, c8 = idx & 7;
            __pipeline_memcpy_async(As + row * GH_LD + c8 * 8,
                                    A + (size_t)(m0 + row) * K + k0 + c8 * 8, 16);
        }
#pragma unroll
        for (int j = 0; j < 8; j++) {
            int idx = tid + j * 256;
            int row = idx >> 3, c8 = idx & 7;
            __pipeline_memcpy_async(Bs + row * GH_LD + c8 * 8,
                                    B + (size_t)(n0 + row) * K + k0 + c8 * 8, 16);
        }
        __pipeline_commit();
    };

    load_stage(0, 0);

    for (int kt = 0; kt < NT; kt++) {
        if (kt + 1 < NT) {
            load_stage((kt + 1) & 1, (kt + 1) * 64);
            __pipeline_wait_prior(1);
        } else {
            __pipeline_wait_prior(0);
        }
        __syncthreads();
        __half* As = smh + (kt & 1) * GH_STAGE_HALVES;
        __half* Bs = As + 128 * GH_LD;
#pragma unroll
        for (int kk = 0; kk < 64; kk += 16) {
            wmma::fragment<wmma::matrix_a, 16, 16, 16, __half, wmma::row_major> fa[4];
            wmma::fragment<wmma::matrix_b, 16, 16, 16, __half, wmma::col_major> fb[4];
#pragma unroll
            for (int mi = 0; mi < 4; mi++)
                wmma::load_matrix_sync(fa[mi], As + (wm * 64 + mi * 16) * GH_LD + kk, GH_LD);
#pragma unroll
            for (int nj = 0; nj < 4; nj++)
                wmma::load_matrix_sync(fb[nj], Bs + (wn * 64 + nj * 16) * GH_LD + kk, GH_LD);
#pragma unroll
            for (int mi = 0; mi < 4; mi++)
#pragma unroll
                for (int nj = 0; nj < 4; nj++)
                    wmma::mma_sync(acc[mi][nj], fa[mi], fb[nj], acc[mi][nj]);
        }
        __syncthreads();
    }
    __syncthreads();

    float* slab = ((float*)smh) + w * 1024;
#pragma unroll
    for (int mi = 0; mi < 4; mi++) {
#pragma unroll
        for (int nj = 0; nj < 4; nj++)
            wmma::store_matrix_sync(slab + nj * 16, acc[mi][nj], 64, wmma::mem_row_major);
        __syncwarp();
#pragma unroll 4
        for (int i = 0; i < 32; i++) {
            int idx = i * 32 + lane;
            int r = idx >> 6;
            int c = idx & 63;
            float v = slab[r * 64 + c] + __ldg(&bias[n0 + wn * 64 + c]);
            C[(size_t)(m0 + wm * 64 + mi * 16 + r) * N + n0 + wn * 64 + c] = v;
        }
        __syncwarp();
    }
}

// ---------------- persistent LSTM layer pass (fp16 datapath) -----------------
__global__ void __launch_bounds__(256, 1) lstm_pass(
    const float* __restrict__ Gpre, const float* __restrict__ Whh,
    const __half* __restrict__ h0, const float* __restrict__ c0,
    __half* __restrict__ y, float* __restrict__ hout, float* __restrict__ cout, int pass)
{
    extern __shared__ __half smp[];
    __half* ws = smp;                       // [32][WH_LD]
    __half* hs = smp + 32 * WH_LD;          // [16][WH_LD]
    float* red = (float*)(smp + 48 * WH_LD);  // 8 x [16][36]
    const int tid = threadIdx.x;
    const int cta = blockIdx.x;
    const int w   = tid >> 5;

    for (int i = tid; i < 32 * 256; i += 256) {
        int r = i >> 8, c = i & 255;
        int grow = (r >> 3) * HID + cta * 8 + (r & 7);
        float4 v = __ldg((const float4*)(Whh + (size_t)grow * HID) + c);
        ((__half2*)(ws + r * WH_LD + c * 4))[0] = __floats2half2_rn(v.x, v.y);
        ((__half2*)(ws + r * WH_LD + c * 4))[1] = __floats2half2_rn(v.z, v.w);
    }
    __syncthreads();

    volatile int* vd = (volatile int*)&d_done[pass];
    const int b  = tid >> 3;
    const int du = tid & 7;
    const int j  = cta * 8 + du;
    float creg = 0.0f;
    if (tid < 128) creg = c0[b * HID + j];

#pragma unroll 1
    for (int t = 0; t < S_LEN; t++) {
        float gp0 = 0.f, gp1 = 0.f, gp2 = 0.f, gp3 = 0.f;
        if (tid < 128) {
            const float* g = Gpre + (size_t)t * BATCH * G4 + b * G4 + j;
            gp0 = __ldg(g); gp1 = __ldg(g + HID); gp2 = __ldg(g + 2*HID); gp3 = __ldg(g + 3*HID);
        }
        if (t > 0) { if (tid == 0) { while (*vd < 128 * t) { } } }
        __syncthreads();

        {
            const uint4* src = (t == 0) ? (const uint4*)h0
                                        : (const uint4*)d_hbuf[(t + 1) & 1];
#pragma unroll
            for (int q = 0; q < 8; q++) {
                int i = tid + q * 256;         // 0..2047
                int r = i >> 7, c = i & 127;
                uint4 v;
                asm volatile("ld.global.cg.v4.u32 {%0,%1,%2,%3}, [%4];"
                             : "=r"(v.x), "=r"(v.y), "=r"(v.z), "=r"(v.w)
                             : "l"(src + i));
                ((uint4*)(hs + r * WH_LD))[c] = v;
            }
        }
        __syncthreads();

        {
            wmma::fragment<wmma::accumulator, 16, 16, 16, float> a0, a1;
            wmma::fill_fragment(a0, 0.0f);
            wmma::fill_fragment(a1, 0.0f);
#pragma unroll
            for (int kk = 0; kk < 128; kk += 16) {
                int k = w * 128 + kk;
                wmma::fragment<wmma::matrix_a, 16, 16, 16, __half, wmma::row_major> fa;
                wmma::fragment<wmma::matrix_b, 16, 16, 16, __half, wmma::col_major> f0, f1;
                wmma::load_matrix_sync(fa, hs + k, WH_LD);
                wmma::load_matrix_sync(f0, ws + k, WH_LD);
                wmma::load_matrix_sync(f1, ws + 16 * WH_LD + k, WH_LD);
                wmma::mma_sync(a0, fa, f0, a0);
                wmma::mma_sync(a1, fa, f1, a1);
            }
            wmma::store_matrix_sync(red + w * 576,      a0, 36, wmma::mem_row_major);
            wmma::store_matrix_sync(red + w * 576 + 16, a1, 36, wmma::mem_row_major);
        }
        __syncthreads();

        if (tid < 128) {
            float s0 = gp0, s1 = gp1, s2 = gp2, s3 = gp3;
#pragma unroll
            for (int p = 0; p < 8; p++) {
                const float* rp = red + p * 576 + b * 36;
                s0 += rp[du]; s1 += rp[8 + du]; s2 += rp[16 + du]; s3 += rp[24 + du];
            }
            float c = sigf(s1) * creg + sigf(s0) * tanhf(s2);
            float h = sigf(s3) * tanhf(c);
            creg = c;
            __half hh = __float2half_rn(h);
            d_hbuf[t & 1][b * HID + j] = hh;
            y[(size_t)t * BATCH * HID + b * HID + j] = hh;
            if (t == S_LEN - 1) { hout[b * HID + j] = h; cout[b * HID + j] = c; }
        }
        __threadfence();
        __syncthreads();
        if (tid == 0) atomicAdd(&d_done[pass], 1);
    }
}

__global__ void latent_kernel(const float* __restrict__ latW, const float* __restrict__ latb) {
    __shared__ float hesh[HID];
    int blk = blockIdx.x;
    int which = blk >> 10;
    int rem = blk & 1023;
    int b = rem >> 6;
    int jg = rem & 63;
    const float* he = which ? d_he1 : d_he0;
    __half* dh = which ? d_dh1H : d_dh0H;
    for (int i = threadIdx.x; i < HID; i += 256) hesh[i] = he[b * HID + i];
    __syncthreads();
    int w = threadIdx.x >> 5, lane = threadIdx.x & 31;
#pragma unroll
    for (int q = 0; q < 2; q++) {
        int j = jg * 16 + w * 2 + q;
        const float* wr = latW + (size_t)j * HID;
        float s = 0.0f;
        for (int k = lane; k < HID; k += 32) s += wr[k] * hesh[k];
#pragma unroll
        for (int o = 16; o; o >>= 1) s += __shfl_xor_sync(0xFFFFFFFFu, s, o);
        if (lane == 0) dh[b * HID + j] = __float2half_rn(s + latb[j]);
    }
}

extern "C" void kernel_launch(void* const* d_in, const int* in_sizes, int n_in,
                              void* d_out, int out_size) {
    const int*   tokens   = (const int*)  d_in[0];
    const float* emb      = (const float*)d_in[1];
    const float* dec_bias = (const float*)d_in[2];
    const float* Wih0     = (const float*)d_in[3];
    const float* Whh0     = (const float*)d_in[4];
    const float* bih0     = (const float*)d_in[5];
    const float* bhh0     = (const float*)d_in[6];
    const float* Wih1     = (const float*)d_in[7];
    const float* Whh1     = (const float*)d_in[8];
    const float* bih1     = (const float*)d_in[9];
    const float* bhh1     = (const float*)d_in[10];
    const float* latW     = (const float*)d_in[11];
    const float* latb     = (const float*)d_in[12];
    float* out = (float*)d_out;

    cudaFuncSetAttribute(gemm_h,    cudaFuncAttributeMaxDynamicSharedMemorySize, GEMM_SMEM_BYTES);
    cudaFuncSetAttribute(lstm_pass, cudaFuncAttributeMaxDynamicSharedMemorySize, PASS_SMEM_BYTES);

    float *pG0, *pG1, *pbc0, *pbc1, *pZF;
    float *phe0, *pce0, *phe1, *pce1;
    __half *pXH, *pY0H, *pD0H, *pD1H, *pembH, *pWH0, *pWH1;
    __half *pZH, *pdh0H, *pdh1H;
    cudaGetSymbolAddress((void**)&pG0,   d_G0);
    cudaGetSymbolAddress((void**)&pG1,   d_G1);
    cudaGetSymbolAddress((void**)&pbc0,  d_bc0);
    cudaGetSymbolAddress((void**)&pbc1,  d_bc1);
    cudaGetSymbolAddress((void**)&pZF,   d_zerosF);
    cudaGetSymbolAddress((void**)&phe0,  d_he0);
    cudaGetSymbolAddress((void**)&pce0,  d_ce0);
    cudaGetSymbolAddress((void**)&phe1,  d_he1);
    cudaGetSymbolAddress((void**)&pce1,  d_ce1);
    cudaGetSymbolAddress((void**)&pXH,   d_X);
    cudaGetSymbolAddress((void**)&pY0H,  d_Y0);
    cudaGetSymbolAddress((void**)&pD0H,  d_D0);
    cudaGetSymbolAddress((void**)&pD1H,  d_D1);
    cudaGetSymbolAddress((void**)&pembH, d_embH);
    cudaGetSymbolAddress((void**)&pWH0,  d_WH0);
    cudaGetSymbolAddress((void**)&pWH1,  d_WH1);
    cudaGetSymbolAddress((void**)&pZH,   d_zerosH);
    cudaGetSymbolAddress((void**)&pdh0H, d_dh0H);
    cudaGetSymbolAddress((void**)&pdh1H, d_dh1H);

    init_kernel<<<16, 256>>>(bih0, bhh0, bih1, bhh1);
    tohalf_kernel<<<(VOC*HID/4 + 255)/256, 256>>>(emb,  pembH, VOC*HID/4);
    tohalf_kernel<<<(G4*HID/4 + 255)/256, 256>>>(Wih0, pWH0,  G4*HID/4);
    tohalf_kernel<<<(G4*HID/4 + 255)/256, 256>>>(Wih1, pWH1,  G4*HID/4);
    embed_kernel<<<ROWS, 256>>>(tokens);

    gemm_h<<<dim3(16, 16), 256, GEMM_SMEM_BYTES>>>(pXH, pWH0, pbc0, pG0, G4, HID);
    lstm_pass<<<128, 256, PASS_SMEM_BYTES>>>(pG0, Whh0, pZH, pZF, pY0H, phe0, pce0, 0);
    gemm_h<<<dim3(16, 16), 256, GEMM_SMEM_BYTES>>>(pY0H, pWH1, pbc1, pG1, G4, HID);
    lstm_pass<<<128, 256, PASS_SMEM_BYTES>>>(pG1, Whh1, pZH, pZF, pD1H, phe1, pce1, 1);
    latent_kernel<<<2048, 256>>>(latW, latb);
    lstm_pass<<<128, 256, PASS_SMEM_BYTES>>>(pG0, Whh0, pdh0H, pce0, pD0H, phe0, pce0, 2);
    gemm_h<<<dim3(16, 16), 256, GEMM_SMEM_BYTES>>>(pD0H, pWH1, pbc1, pG1, G4, HID);
    lstm_pass<<<128, 256, PASS_SMEM_BYTES>>>(pG1, Whh1, pdh1H, pce1, pD1H, phe1, pce1, 3);
    gemm_h<<<dim3(16, 125), 256, GEMM_SMEM_BYTES>>>(pD1H, pembH, dec_bias, out, VOC, HID);
}

// round 16
// speedup vs baseline: 3.3290x; 1.0779x over previous
#include <cuda_runtime.h>
#include <cuda_fp16.h>
#include <cuda_pipeline.h>
#include <mma.h>
#include <cstdint>
#include <cstddef>
#include <math.h>

using namespace nvcuda;

#define S_LEN 128
#define BATCH 16
#define HID   1024
#define G4    4096
#define ROWS  2048            // S*B
#define VOC   32000
#define WH_LD 1040            // lstm smem leading dim (halves): 1024 + 16
#define PASS_SMEM_BYTES ((32*WH_LD + 16*WH_LD) * 2 + 8*576*4)  // 118272
#define DUAL_SMEM_BYTES ((64*WH_LD + 32*WH_LD) * 2 + 8*576*4)  // 218112
#define GH_LD 72              // gemm smem row pad (halves): 64 data + 8 pad
#define GH_STAGE_HALVES ((128 + 256) * GH_LD)                  // 27648
#define GEMM_SMEM_BYTES (2 * GH_STAGE_HALVES * 2)              // 110592

// ---------------- static device scratch (no cudaMalloc anywhere) -------------
__device__ __align__(16) __half d_embH[VOC*HID];
__device__ __align__(16) __half d_WH0[G4*HID];
__device__ __align__(16) __half d_WH1[G4*HID];
__device__ __align__(16) __half d_X [ROWS*HID];
__device__ __align__(16) __half d_Y0[ROWS*HID];
__device__ __align__(16) __half d_D0[ROWS*HID];
__device__ __align__(16) __half d_D1[ROWS*HID];
__device__ __align__(16) __half d_hbuf[2][BATCH*HID];    // single-pass h ring
__device__ __align__(16) __half d_hbufA[2][BATCH*HID];   // dual chain A ring
__device__ __align__(16) __half d_hbufB[2][BATCH*HID];   // dual chain B ring
__device__ __align__(16) __half d_dh0H[BATCH*HID];
__device__ __align__(16) __half d_dh1H[BATCH*HID];
__device__ __align__(16) __half d_zerosH[BATCH*HID];
__device__ __align__(16) float d_zerosF[BATCH*HID];
__device__ __align__(16) float d_G0[ROWS*G4];
__device__ __align__(16) float d_G1[ROWS*G4];
__device__ __align__(16) float d_he0[BATCH*HID];
__device__ __align__(16) float d_ce0[BATCH*HID];
__device__ __align__(16) float d_he1[BATCH*HID];
__device__ __align__(16) float d_ce1[BATCH*HID];
__device__ __align__(16) float d_bc0[G4];
__device__ __align__(16) float d_bc1[G4];
__device__ int d_done[4];

__device__ __forceinline__ float sigf(float x) { return 1.0f / (1.0f + expf(-x)); }

__global__ void init_kernel(const float* __restrict__ bih0, const float* __restrict__ bhh0,
                            const float* __restrict__ bih1, const float* __restrict__ bhh1) {
    int tid = blockIdx.x * blockDim.x + threadIdx.x;   // 4096 threads
    if (tid < 4) d_done[tid] = 0;
    for (int i = tid; i < BATCH*HID; i += 4096) {
        d_zerosH[i] = __float2half(0.0f);
        d_zerosF[i] = 0.0f;
    }
    if (tid < G4) {
        d_bc0[tid] = bih0[tid] + bhh0[tid];
        d_bc1[tid] = bih1[tid] + bhh1[tid];
    }
}

__global__ void tohalf_kernel(const float* __restrict__ src, __half* __restrict__ dst, int n4) {
    int i = blockIdx.x * blockDim.x + threadIdx.x;
    if (i < n4) {
        float4 v = ((const float4*)src)[i];
        ((__half2*)dst)[2*i]   = __floats2half2_rn(v.x, v.y);
        ((__half2*)dst)[2*i+1] = __floats2half2_rn(v.z, v.w);
    }
}

__global__ void embed_kernel(const int* __restrict__ tokens) {
    int row = blockIdx.x;                              // t*B + b
    int tok = tokens[row];
    const uint4* src = (const uint4*)(d_embH + (size_t)tok * HID);
    uint4* dst = (uint4*)(d_X + (size_t)row * HID);
    for (int i = threadIdx.x; i < HID/8; i += blockDim.x) dst[i] = src[i];
}

// ---------------- fp16 WMMA GEMM: CTA 128x256, warp 64x64, 2-stage cp.async --
__global__ void __launch_bounds__(256) gemm_h(
    const __half* __restrict__ A, const __half* __restrict__ B,
    const float* __restrict__ bias, float* __restrict__ C, int N, int K)
{
    extern __shared__ __half smh[];
    const int tid = threadIdx.x;
    const int m0 = blockIdx.x * 128;
    const int n0 = blockIdx.y * 256;
    const int w  = tid >> 5;
    const int lane = tid & 31;
    const int wm = w & 1;
    const int wn = w >> 1;

    wmma::fragment<wmma::accumulator, 16, 16, 16, float> acc[4][4];
#pragma unroll
    for (int mi = 0; mi < 4; mi++)
#pragma unroll
        for (int nj = 0; nj < 4; nj++) wmma::fill_fragment(acc[mi][nj], 0.0f);

    const int NT = K / 64;

    auto load_stage = [&](int s, int k0) {
        __half* As = smh + s * GH_STAGE_HALVES;
        __half* Bs = As + 128 * GH_LD;
#pragma unroll
        for (int j = 0; j < 4; j++) {
            int idx = tid + j * 256;
            int row = idx >> 3, c8 = idx & 7;
            __pipeline_memcpy_async(As + row * GH_LD + c8 * 8,
                                    A + (size_t)(m0 + row) * K + k0 + c8 * 8, 16);
        }
#pragma unroll
        for (int j = 0; j < 8; j++) {
            int idx = tid + j * 256;
            int row = idx >> 3, c8 = idx & 7;
            __pipeline_memcpy_async(Bs + row * GH_LD + c8 * 8,
                                    B + (size_t)(n0 + row) * K + k0 + c8 * 8, 16);
        }
        __pipeline_commit();
    };

    load_stage(0, 0);

    for (int kt = 0; kt < NT; kt++) {
        if (kt + 1 < NT) {
            load_stage((kt + 1) & 1, (kt + 1) * 64);
            __pipeline_wait_prior(1);
        } else {
            __pipeline_wait_prior(0);
        }
        __syncthreads();
        __half* As = smh + (kt & 1) * GH_STAGE_HALVES;
        __half* Bs = As + 128 * GH_LD;
#pragma unroll
        for (int kk = 0; kk < 64; kk += 16) {
            wmma::fragment<wmma::matrix_a, 16, 16, 16, __half, wmma::row_major> fa[4];
            wmma::fragment<wmma::matrix_b, 16, 16, 16, __half, wmma::col_major> fb[4];
#pragma unroll
            for (int mi = 0; mi < 4; mi++)
                wmma::load_matrix_sync(fa[mi], As + (wm * 64 + mi * 16) * GH_LD + kk, GH_LD);
#pragma unroll
            for (int nj = 0; nj < 4; nj++)
                wmma::load_matrix_sync(fb[nj], Bs + (wn * 64 + nj * 16) * GH_LD + kk, GH_LD);
#pragma unroll
            for (int mi = 0; mi < 4; mi++)
#pragma unroll
                for (int nj = 0; nj < 4; nj++)
                    wmma::mma_sync(acc[mi][nj], fa[mi], fb[nj], acc[mi][nj]);
        }
        __syncthreads();
    }
    __syncthreads();

    float* slab = ((float*)smh) + w * 1024;
#pragma unroll
    for (int mi = 0; mi < 4; mi++) {
#pragma unroll
        for (int nj = 0; nj < 4; nj++)
            wmma::store_matrix_sync(slab + nj * 16, acc[mi][nj], 64, wmma::mem_row_major);
        __syncwarp();
#pragma unroll 4
        for (int i = 0; i < 32; i++) {
            int idx = i * 32 + lane;
            int r = idx >> 6;
            int c = idx & 63;
            float v = slab[r * 64 + c] + __ldg(&bias[n0 + wn * 64 + c]);
            C[(size_t)(m0 + wm * 64 + mi * 16 + r) * N + n0 + wn * 64 + c] = v;
        }
        __syncwarp();
    }
}

// ---------------- single persistent LSTM pass (exact 2391us-proven body) -----
__global__ void __launch_bounds__(256, 1) lstm_pass(
    const float* __restrict__ Gpre, const float* __restrict__ Whh,
    const __half* __restrict__ h0, const float* __restrict__ c0,
    __half* __restrict__ y, float* __restrict__ hout, float* __restrict__ cout, int pass)
{
    extern __shared__ __half smp[];
    __half* ws = smp;                         // [32][WH_LD]
    __half* hs = smp + 32 * WH_LD;            // [16][WH_LD]
    float* red = (float*)(smp + 48 * WH_LD);  // 8 x [16][36]
    const int tid = threadIdx.x;
    const int cta = blockIdx.x;
    const int w   = tid >> 5;

    for (int i = tid; i < 32 * 256; i += 256) {
        int r = i >> 8, c = i & 255;
        int grow = (r >> 3) * HID + cta * 8 + (r & 7);
        float4 v = __ldg((const float4*)(Whh + (size_t)grow * HID) + c);
        ((__half2*)(ws + r * WH_LD + c * 4))[0] = __floats2half2_rn(v.x, v.y);
        ((__half2*)(ws + r * WH_LD + c * 4))[1] = __floats2half2_rn(v.z, v.w);
    }
    __syncthreads();

    volatile int* vd = (volatile int*)&d_done[pass];
    const int b  = tid >> 3;
    const int du = tid & 7;
    const int j  = cta * 8 + du;
    float creg = 0.0f;
    if (tid < 128) creg = c0[b * HID + j];

#pragma unroll 1
    for (int t = 0; t < S_LEN; t++) {
        float gp0 = 0.f, gp1 = 0.f, gp2 = 0.f, gp3 = 0.f;
        if (tid < 128) {
            const float* g = Gpre + (size_t)t * BATCH * G4 + b * G4 + j;
            gp0 = __ldg(g); gp1 = __ldg(g + HID); gp2 = __ldg(g + 2*HID); gp3 = __ldg(g + 3*HID);
        }
        if (t > 0) { if (tid == 0) { while (*vd < 128 * t) { } } }
        __syncthreads();

        {
            const uint4* src = (t == 0) ? (const uint4*)h0
                                        : (const uint4*)d_hbuf[(t + 1) & 1];
#pragma unroll
            for (int q = 0; q < 8; q++) {
                int i = tid + q * 256;         // 0..2047
                int r = i >> 7, c = i & 127;
                uint4 v;
                asm volatile("ld.global.cg.v4.u32 {%0,%1,%2,%3}, [%4];"
                             : "=r"(v.x), "=r"(v.y), "=r"(v.z), "=r"(v.w)
                             : "l"(src + i));
                ((uint4*)(hs + r * WH_LD))[c] = v;
            }
        }
        __syncthreads();

        {
            wmma::fragment<wmma::accumulator, 16, 16, 16, float> a0, a1;
            wmma::fill_fragment(a0, 0.0f);
            wmma::fill_fragment(a1, 0.0f);
#pragma unroll
            for (int kk = 0; kk < 128; kk += 16) {
                int k = w * 128 + kk;
                wmma::fragment<wmma::matrix_a, 16, 16, 16, __half, wmma::row_major> fa;
                wmma::fragment<wmma::matrix_b, 16, 16, 16, __half, wmma::col_major> f0, f1;
                wmma::load_matrix_sync(fa, hs + k, WH_LD);
                wmma::load_matrix_sync(f0, ws + k, WH_LD);
                wmma::load_matrix_sync(f1, ws + 16 * WH_LD + k, WH_LD);
                wmma::mma_sync(a0, fa, f0, a0);
                wmma::mma_sync(a1, fa, f1, a1);
            }
            wmma::store_matrix_sync(red + w * 576,      a0, 36, wmma::mem_row_major);
            wmma::store_matrix_sync(red + w * 576 + 16, a1, 36, wmma::mem_row_major);
        }
        __syncthreads();

        if (tid < 128) {
            float s0 = gp0, s1 = gp1, s2 = gp2, s3 = gp3;
#pragma unroll
            for (int p = 0; p < 8; p++) {
                const float* rp = red + p * 576 + b * 36;
                s0 += rp[du]; s1 += rp[8 + du]; s2 += rp[16 + du]; s3 += rp[24 + du];
            }
            float c = sigf(s1) * creg + sigf(s0) * tanhf(s2);
            float h = sigf(s3) * tanhf(c);
            creg = c;
            __half hh = __float2half_rn(h);
            d_hbuf[t & 1][b * HID + j] = hh;
            y[(size_t)t * BATCH * HID + b * HID + j] = hh;
            if (t == S_LEN - 1) { hout[b * HID + j] = h; cout[b * HID + j] = c; }
        }
        __threadfence();
        __syncthreads();
        if (tid == 0) atomicAdd(&d_done[pass], 1);
    }
}

// ---------------- dual pass: chain A = enc-l1, chain B = dec-l0 --------------
// Same proven sync idiom as lstm_pass; counter d_done[1]; one sync per step.
__global__ void __launch_bounds__(256, 1) dual_pass(
    const float* __restrict__ GpreA, const float* __restrict__ WhhA,   // enc1: G1, Whh1
    const float* __restrict__ GpreB, const float* __restrict__ WhhB,   // dec0: G0, Whh0
    const __half* __restrict__ h0B, const float* __restrict__ c0B,     // dh0H, ce0
    __half* __restrict__ yB,                                           // D0
    float* __restrict__ houtA, float* __restrict__ coutA,              // he1, ce1
    float* __restrict__ houtB, float* __restrict__ coutB)              // he0, ce0 (dump)
{
    extern __shared__ __half smp[];
    __half* wsA = smp;                          // [32][WH_LD]
    __half* wsB = smp + 32 * WH_LD;             // [32][WH_LD]
    __half* hsA = smp + 64 * WH_LD;             // [16][WH_LD]
    __half* hsB = smp + 80 * WH_LD;             // [16][WH_LD]
    float* red  = (float*)(smp + 96 * WH_LD);   // 8 x [16][36]
    const int tid = threadIdx.x;
    const int cta = blockIdx.x;
    const int w   = tid >> 5;

    for (int i = tid; i < 32 * 256; i += 256) {
        int r = i >> 8, c = i & 255;
        int grow = (r >> 3) * HID + cta * 8 + (r & 7);
        float4 va = __ldg((const float4*)(WhhA + (size_t)grow * HID) + c);
        ((__half2*)(wsA + r * WH_LD + c * 4))[0] = __floats2half2_rn(va.x, va.y);
        ((__half2*)(wsA + r * WH_LD + c * 4))[1] = __floats2half2_rn(va.z, va.w);
        float4 vb = __ldg((const float4*)(WhhB + (size_t)grow * HID) + c);
        ((__half2*)(wsB + r * WH_LD + c * 4))[0] = __floats2half2_rn(vb.x, vb.y);
        ((__half2*)(wsB + r * WH_LD + c * 4))[1] = __floats2half2_rn(vb.z, vb.w);
    }
    __syncthreads();

    volatile int* vd = (volatile int*)&d_done[1];
    const int b  = tid >> 3;
    const int du = tid & 7;
    const int j  = cta * 8 + du;
    float cA = 0.0f, cB = 0.0f;                // enc1 cell starts at zero
    if (tid < 128) cB = c0B[b * HID + j];

#pragma unroll 1
    for (int t = 0; t < S_LEN; t++) {
        float ga0 = 0.f, ga1 = 0.f, ga2 = 0.f, ga3 = 0.f;
        float gb0 = 0.f, gb1 = 0.f, gb2 = 0.f, gb3 = 0.f;
        if (tid < 128) {
            const float* ga = GpreA + (size_t)t * BATCH * G4 + b * G4 + j;
            ga0 = __ldg(ga); ga1 = __ldg(ga + HID); ga2 = __ldg(ga + 2*HID); ga3 = __ldg(ga + 3*HID);
            const float* gb = GpreB + (size_t)t * BATCH * G4 + b * G4 + j;
            gb0 = __ldg(gb); gb1 = __ldg(gb + HID); gb2 = __ldg(gb + 2*HID); gb3 = __ldg(gb + 3*HID);
        }
        if (t > 0) { if (tid == 0) { while (*vd < 128 * t) { } } }
        __syncthreads();

        {
            const uint4* srcA = (t == 0) ? (const uint4*)d_zerosH
                                         : (const uint4*)d_hbufA[(t + 1) & 1];
            const uint4* srcB = (t == 0) ? (const uint4*)h0B
                                         : (const uint4*)d_hbufB[(t + 1) & 1];
#pragma unroll
            for (int q = 0; q < 8; q++) {
                int i = tid + q * 256;         // 0..2047
                int r = i >> 7, c = i & 127;
                uint4 va, vb;
                asm volatile("ld.global.cg.v4.u32 {%0,%1,%2,%3}, [%4];"
                             : "=r"(va.x), "=r"(va.y), "=r"(va.z), "=r"(va.w)
                             : "l"(srcA + i));
                ((uint4*)(hsA + r * WH_LD))[c] = va;
                asm volatile("ld.global.cg.v4.u32 {%0,%1,%2,%3}, [%4];"
                             : "=r"(vb.x), "=r"(vb.y), "=r"(vb.z), "=r"(vb.w)
                             : "l"(srcB + i));
                ((uint4*)(hsB + r * WH_LD))[c] = vb;
            }
        }
        __syncthreads();

        // ---- chain A matmul + elementwise ----
        {
            wmma::fragment<wmma::accumulator, 16, 16, 16, float> a0, a1;
            wmma::fill_fragment(a0, 0.0f);
            wmma::fill_fragment(a1, 0.0f);
#pragma unroll
            for (int kk = 0; kk < 128; kk += 16) {
                int k = w * 128 + kk;
                wmma::fragment<wmma::matrix_a, 16, 16, 16, __half, wmma::row_major> fa;
                wmma::fragment<wmma::matrix_b, 16, 16, 16, __half, wmma::col_major> f0, f1;
                wmma::load_matrix_sync(fa, hsA + k, WH_LD);
                wmma::load_matrix_sync(f0, wsA + k, WH_LD);
                wmma::load_matrix_sync(f1, wsA + 16 * WH_LD + k, WH_LD);
                wmma::mma_sync(a0, fa, f0, a0);
                wmma::mma_sync(a1, fa, f1, a1);
            }
            wmma::store_matrix_sync(red + w * 576,      a0, 36, wmma::mem_row_major);
            wmma::store_matrix_sync(red + w * 576 + 16, a1, 36, wmma::mem_row_major);
        }
        __syncthreads();
        float hAv = 0.f, cAv = 0.f;
        if (tid < 128) {
            float s0 = ga0, s1 = ga1, s2 = ga2, s3 = ga3;
#pragma unroll
            for (int p = 0; p < 8; p++) {
                const float* rp = red + p * 576 + b * 36;
                s0 += rp[du]; s1 += rp[8 + du]; s2 += rp[16 + du]; s3 += rp[24 + du];
            }
            cA = sigf(s1) * cA + sigf(s0) * tanhf(s2);
            float h = sigf(s3) * tanhf(cA);
            hAv = h; cAv = cA;
            d_hbufA[t & 1][b * HID + j] = __float2half_rn(h);
        }
        __syncthreads();   // chain-A red reads complete before chain-B stores

        // ---- chain B matmul + elementwise ----
        {
            wmma::fragment<wmma::accumulator, 16, 16, 16, float> a0, a1;
            wmma::fill_fragment(a0, 0.0f);
            wmma::fill_fragment(a1, 0.0f);
#pragma unroll
            for (int kk = 0; kk < 128; kk += 16) {
                int k = w * 128 + kk;
                wmma::fragment<wmma::matrix_a, 16, 16, 16, __half, wmma::row_major> fa;
                wmma::fragment<wmma::matrix_b, 16, 16, 16, __half, wmma::col_major> f0, f1;
                wmma::load_matrix_sync(fa, hsB + k, WH_LD);
                wmma::load_matrix_sync(f0, wsB + k, WH_LD);
                wmma::load_matrix_sync(f1, wsB + 16 * WH_LD + k, WH_LD);
                wmma::mma_sync(a0, fa, f0, a0);
                wmma::mma_sync(a1, fa, f1, a1);
            }
            wmma::store_matrix_sync(red + w * 576,      a0, 36, wmma::mem_row_major);
            wmma::store_matrix_sync(red + w * 576 + 16, a1, 36, wmma::mem_row_major);
        }
        __syncthreads();
        if (tid < 128) {
            float s0 = gb0, s1 = gb1, s2 = gb2, s3 = gb3;
#pragma unroll
            for (int p = 0; p < 8; p++) {
                const float* rp = red + p * 576 + b * 36;
                s0 += rp[du]; s1 += rp[8 + du]; s2 += rp[16 + du]; s3 += rp[24 + du];
            }
            cB = sigf(s1) * cB + sigf(s0) * tanhf(s2);
            float h = sigf(s3) * tanhf(cB);
            __half hh = __float2half_rn(h);
            d_hbufB[t & 1][b * HID + j] = hh;
            yB[(size_t)t * BATCH * HID + b * HID + j] = hh;
            if (t == S_LEN - 1) {
                houtA[b * HID + j] = hAv; coutA[b * HID + j] = cAv;
                houtB[b * HID + j] = h;   coutB[b * HID + j] = cB;
            }
        }
        __threadfence();
        __syncthreads();
        if (tid == 0) atomicAdd(&d_done[1], 1);
    }
}

// ---------------- latent: dh = fp16(he @ latW^T + latb) ----------------------
__global__ void latent_kernel(const float* __restrict__ latW, const float* __restrict__ latb,
                              int which) {
    __shared__ float hesh[HID];
    int rem = blockIdx.x;          // 0..1023
    int b = rem >> 6;
    int jg = rem & 63;
    const float* he = which ? d_he1 : d_he0;
    __half* dh = which ? d_dh1H : d_dh0H;
    for (int i = threadIdx.x; i < HID; i += 256) hesh[i] = he[b * HID + i];
    __syncthreads();
    int w = threadIdx.x >> 5, lane = threadIdx.x & 31;
#pragma unroll
    for (int q = 0; q < 2; q++) {
        int j = jg * 16 + w * 2 + q;
        const float* wr = latW + (size_t)j * HID;
        float s = 0.0f;
        for (int k = lane; k < HID; k += 32) s += wr[k] * hesh[k];
#pragma unroll
        for (int o = 16; o; o >>= 1) s += __shfl_xor_sync(0xFFFFFFFFu, s, o);
        if (lane == 0) dh[b * HID + j] = __float2half_rn(s + latb[j]);
    }
}

extern "C" void kernel_launch(void* const* d_in, const int* in_sizes, int n_in,
                              void* d_out, int out_size) {
    const int*   tokens   = (const int*)  d_in[0];
    const float* emb      = (const float*)d_in[1];
    const float* dec_bias = (const float*)d_in[2];
    const float* Wih0     = (const float*)d_in[3];
    const float* Whh0     = (const float*)d_in[4];
    const float* bih0     = (const float*)d_in[5];
    const float* bhh0     = (const float*)d_in[6];
    const float* Wih1     = (const float*)d_in[7];
    const float* Whh1     = (const float*)d_in[8];
    const float* bih1     = (const float*)d_in[9];
    const float* bhh1     = (const float*)d_in[10];
    const float* latW     = (const float*)d_in[11];
    const float* latb     = (const float*)d_in[12];
    float* out = (float*)d_out;

    cudaFuncSetAttribute(gemm_h,    cudaFuncAttributeMaxDynamicSharedMemorySize, GEMM_SMEM_BYTES);
    cudaFuncSetAttribute(lstm_pass, cudaFuncAttributeMaxDynamicSharedMemorySize, PASS_SMEM_BYTES);
    cudaFuncSetAttribute(dual_pass, cudaFuncAttributeMaxDynamicSharedMemorySize, DUAL_SMEM_BYTES);

    float *pG0, *pG1, *pbc0, *pbc1, *pZF;
    float *phe0, *pce0, *phe1, *pce1;
    __half *pXH, *pY0H, *pD0H, *pD1H, *pembH, *pWH0, *pWH1;
    __half *pZH, *pdh0H, *pdh1H;
    cudaGetSymbolAddress((void**)&pG0,   d_G0);
    cudaGetSymbolAddress((void**)&pG1,   d_G1);
    cudaGetSymbolAddress((void**)&pbc0,  d_bc0);
    cudaGetSymbolAddress((void**)&pbc1,  d_bc1);
    cudaGetSymbolAddress((void**)&pZF,   d_zerosF);
    cudaGetSymbolAddress((void**)&phe0,  d_he0);
    cudaGetSymbolAddress((void**)&pce0,  d_ce0);
    cudaGetSymbolAddress((void**)&phe1,  d_he1);
    cudaGetSymbolAddress((void**)&pce1,  d_ce1);
    cudaGetSymbolAddress((void**)&pXH,   d_X);
    cudaGetSymbolAddress((void**)&pY0H,  d_Y0);
    cudaGetSymbolAddress((void**)&pD0H,  d_D0);
    cudaGetSymbolAddress((void**)&pD1H,  d_D1);
    cudaGetSymbolAddress((void**)&pembH, d_embH);
    cudaGetSymbolAddress((void**)&pWH0,  d_WH0);
    cudaGetSymbolAddress((void**)&pWH1,  d_WH1);
    cudaGetSymbolAddress((void**)&pZH,   d_zerosH);
    cudaGetSymbolAddress((void**)&pdh0H, d_dh0H);
    cudaGetSymbolAddress((void**)&pdh1H, d_dh1H);

    init_kernel<<<16, 256>>>(bih0, bhh0, bih1, bhh1);
    tohalf_kernel<<<(VOC*HID/4 + 255)/256, 256>>>(emb,  pembH, VOC*HID/4);
    tohalf_kernel<<<(G4*HID/4 + 255)/256, 256>>>(Wih0, pWH0,  G4*HID/4);
    tohalf_kernel<<<(G4*HID/4 + 255)/256, 256>>>(Wih1, pWH1,  G4*HID/4);
    embed_kernel<<<ROWS, 256>>>(tokens);

    // G0 = X @ Wih0^T + b0 (shared by enc-l0 and teacher-forced dec-l0)
    gemm_h<<<dim3(16, 16), 256, GEMM_SMEM_BYTES>>>(pXH, pWH0, pbc0, pG0, G4, HID);
    // encoder layer 0 (counter slot 0)
    lstm_pass<<<128, 256, PASS_SMEM_BYTES>>>(pG0, Whh0, pZH, pZF, pY0H, phe0, pce0, 0);
    // latent for decoder layer 0 (he0 -> dh0H; he0/ce0 then dead except dual's own reads)
    latent_kernel<<<1024, 256>>>(latW, latb, 0);
    // G1 = Y0 @ Wih1^T + b1
    gemm_h<<<dim3(16, 16), 256, GEMM_SMEM_BYTES>>>(pY0H, pWH1, pbc1, pG1, G4, HID);
    // enc-l1 || dec-l0 in one grid-synced kernel (counter slot 1)
    dual_pass<<<128, 256, DUAL_SMEM_BYTES>>>(pG1, Whh1, pG0, Whh0,
                                             pdh0H, pce0, pD0H,
                                             phe1, pce1, phe0, pce0);
    // latent for decoder layer 1 (he1 -> dh1H)
    latent_kernel<<<1024, 256>>>(latW, latb, 1);
    // G1d = D0 @ Wih1^T + b1 (G1 free: dual_pass retired)
    gemm_h<<<dim3(16, 16), 256, GEMM_SMEM_BYTES>>>(pD0H, pWH1, pbc1, pG1, G4, HID);
    // decoder layer 1 (counter slot 3); hout/cout dumped into dead he0/ce0
    lstm_pass<<<128, 256, PASS_SMEM_BYTES>>>(pG1, Whh1, pdh1H, pce1, pD1H, phe0, pce0, 3);
    // logits = D1 @ embH^T + dec_bias
    gemm_h<<<dim3(16, 125), 256, GEMM_SMEM_BYTES>>>(pD1H, pembH, dec_bias, out, VOC, HID);
}

// round 17
// speedup vs baseline: 3.4156x; 1.0260x over previous
#include <cuda_runtime.h>
#include <cuda_fp16.h>
#include <cuda_pipeline.h>
#include <mma.h>
#include <cstdint>
#include <cstddef>
#include <math.h>

using namespace nvcuda;

#define S_LEN 128
#define BATCH 16
#define HID   1024
#define G4    4096
#define ROWS  2048            // S*B
#define VOC   32000
#define WH_LD 1040            // lstm smem leading dim (halves): 1024 + 16
#define PASS_SMEM_BYTES ((32*WH_LD + 16*WH_LD) * 2 + 8*576*4)  // 118272
#define DUAL_SMEM_BYTES ((64*WH_LD + 32*WH_LD) * 2 + 8*576*4)  // 218112
#define GH_LD 72              // gemm smem row pad (halves): 64 data + 8 pad
#define GH_STAGE_HALVES ((128 + 256) * GH_LD)                  // 27648
#define GEMM_SMEM_BYTES (2 * GH_STAGE_HALVES * 2)              // 110592

// ---------------- static device scratch (no cudaMalloc anywhere) -------------
__device__ __align__(16) __half d_embH[VOC*HID];
__device__ __align__(16) __half d_WH0[G4*HID];
__device__ __align__(16) __half d_WH1[G4*HID];
__device__ __align__(16) __half d_X [ROWS*HID];
__device__ __align__(16) __half d_Y0[ROWS*HID];
__device__ __align__(16) __half d_D0[ROWS*HID];
__device__ __align__(16) __half d_D1[ROWS*HID];
__device__ __align__(16) __half d_hbuf[2][BATCH*HID];    // single-pass h ring
__device__ __align__(16) __half d_hbufA[2][BATCH*HID];   // dual chain A ring
__device__ __align__(16) __half d_hbufB[2][BATCH*HID];   // dual chain B ring
__device__ __align__(16) __half d_dh0H[BATCH*HID];
__device__ __align__(16) __half d_dh1H[BATCH*HID];
__device__ __align__(16) __half d_zerosH[BATCH*HID];
__device__ __align__(16) float d_zerosF[BATCH*HID];
__device__ __align__(16) float d_G0[ROWS*G4];
__device__ __align__(16) float d_G1[ROWS*G4];
__device__ __align__(16) float d_he0[BATCH*HID];
__device__ __align__(16) float d_ce0[BATCH*HID];
__device__ __align__(16) float d_he1[BATCH*HID];
__device__ __align__(16) float d_ce1[BATCH*HID];
__device__ __align__(16) float d_bc0[G4];
__device__ __align__(16) float d_bc1[G4];
__device__ int d_done[4];

__device__ __forceinline__ float sigf(float x) { return 1.0f / (1.0f + expf(-x)); }

__global__ void init_kernel(const float* __restrict__ bih0, const float* __restrict__ bhh0,
                            const float* __restrict__ bih1, const float* __restrict__ bhh1) {
    int tid = blockIdx.x * blockDim.x + threadIdx.x;   // 4096 threads
    if (tid < 4) d_done[tid] = 0;
    for (int i = tid; i < BATCH*HID; i += 4096) {
        d_zerosH[i] = __float2half(0.0f);
        d_zerosF[i] = 0.0f;
    }
    if (tid < G4) {
        d_bc0[tid] = bih0[tid] + bhh0[tid];
        d_bc1[tid] = bih1[tid] + bhh1[tid];
    }
}

__global__ void tohalf_kernel(const float* __restrict__ src, __half* __restrict__ dst, int n4) {
    int i = blockIdx.x * blockDim.x + threadIdx.x;
    if (i < n4) {
        float4 v = ((const float4*)src)[i];
        ((__half2*)dst)[2*i]   = __floats2half2_rn(v.x, v.y);
        ((__half2*)dst)[2*i+1] = __floats2half2_rn(v.z, v.w);
    }
}

__global__ void embed_kernel(const int* __restrict__ tokens) {
    int row = blockIdx.x;                              // t*B + b
    int tok = tokens[row];
    const uint4* src = (const uint4*)(d_embH + (size_t)tok * HID);
    uint4* dst = (uint4*)(d_X + (size_t)row * HID);
    for (int i = threadIdx.x; i < HID/8; i += blockDim.x) dst[i] = src[i];
}

// ---------------- fp16 WMMA GEMM: CTA 128x256, warp 64x64, 2-stage cp.async --
__global__ void __launch_bounds__(256) gemm_h(
    const __half* __restrict__ A, const __half* __restrict__ B,
    const float* __restrict__ bias, float* __restrict__ C, int N, int K)
{
    extern __shared__ __half smh[];
    const int tid = threadIdx.x;
    const int m0 = blockIdx.x * 128;
    const int n0 = blockIdx.y * 256;
    const int w  = tid >> 5;
    const int lane = tid & 31;
    const int wm = w & 1;
    const int wn = w >> 1;

    wmma::fragment<wmma::accumulator, 16, 16, 16, float> acc[4][4];
#pragma unroll
    for (int mi = 0; mi < 4; mi++)
#pragma unroll
        for (int nj = 0; nj < 4; nj++) wmma::fill_fragment(acc[mi][nj], 0.0f);

    const int NT = K / 64;

    auto load_stage = [&](int s, int k0) {
        __half* As = smh + s * GH_STAGE_HALVES;
        __half* Bs = As + 128 * GH_LD;
#pragma unroll
        for (int j = 0; j < 4; j++) {
            int idx = tid + j * 256;
            int row = idx >> 3, c8 = idx & 7;
            __pipeline_memcpy_async(As + row * GH_LD + c8 * 8,
                                    A + (size_t)(m0 + row) * K + k0 + c8 * 8, 16);
        }
#pragma unroll
        for (int j = 0; j < 8; j++) {
            int idx = tid + j * 256;
            int row = idx >> 3, c8 = idx & 7;
            __pipeline_memcpy_async(Bs + row * GH_LD + c8 * 8,
                                    B + (size_t)(n0 + row) * K + k0 + c8 * 8, 16);
        }
        __pipeline_commit();
    };

    load_stage(0, 0);

    for (int kt = 0; kt < NT; kt++) {
        if (kt + 1 < NT) {
            load_stage((kt + 1) & 1, (kt + 1) * 64);
            __pipeline_wait_prior(1);
        } else {
            __pipeline_wait_prior(0);
        }
        __syncthreads();
        __half* As = smh + (kt & 1) * GH_STAGE_HALVES;
        __half* Bs = As + 128 * GH_LD;
#pragma unroll
        for (int kk = 0; kk < 64; kk += 16) {
            wmma::fragment<wmma::matrix_a, 16, 16, 16, __half, wmma::row_major> fa[4];
            wmma::fragment<wmma::matrix_b, 16, 16, 16, __half, wmma::col_major> fb[4];
#pragma unroll
            for (int mi = 0; mi < 4; mi++)
                wmma::load_matrix_sync(fa[mi], As + (wm * 64 + mi * 16) * GH_LD + kk, GH_LD);
#pragma unroll
            for (int nj = 0; nj < 4; nj++)
                wmma::load_matrix_sync(fb[nj], Bs + (wn * 64 + nj * 16) * GH_LD + kk, GH_LD);
#pragma unroll
            for (int mi = 0; mi < 4; mi++)
#pragma unroll
                for (int nj = 0; nj < 4; nj++)
                    wmma::mma_sync(acc[mi][nj], fa[mi], fb[nj], acc[mi][nj]);
        }
        __syncthreads();
    }
    __syncthreads();

    float* slab = ((float*)smh) + w * 1024;
#pragma unroll
    for (int mi = 0; mi < 4; mi++) {
#pragma unroll
        for (int nj = 0; nj < 4; nj++)
            wmma::store_matrix_sync(slab + nj * 16, acc[mi][nj], 64, wmma::mem_row_major);
        __syncwarp();
#pragma unroll 4
        for (int i = 0; i < 32; i++) {
            int idx = i * 32 + lane;
            int r = idx >> 6;
            int c = idx & 63;
            float v = slab[r * 64 + c] + __ldg(&bias[n0 + wn * 64 + c]);
            C[(size_t)(m0 + wm * 64 + mi * 16 + r) * N + n0 + wn * 64 + c] = v;
        }
        __syncwarp();
    }
}

// ---------------- single persistent LSTM pass (exact 2218us-proven body) -----
__global__ void __launch_bounds__(256, 1) lstm_pass(
    const float* __restrict__ Gpre, const float* __restrict__ Whh,
    const __half* __restrict__ h0, const float* __restrict__ c0,
    __half* __restrict__ y, float* __restrict__ hout, float* __restrict__ cout, int pass)
{
    extern __shared__ __half smp[];
    __half* ws = smp;                         // [32][WH_LD]
    __half* hs = smp + 32 * WH_LD;            // [16][WH_LD]
    float* red = (float*)(smp + 48 * WH_LD);  // 8 x [16][36]
    const int tid = threadIdx.x;
    const int cta = blockIdx.x;
    const int w   = tid >> 5;

    for (int i = tid; i < 32 * 256; i += 256) {
        int r = i >> 8, c = i & 255;
        int grow = (r >> 3) * HID + cta * 8 + (r & 7);
        float4 v = __ldg((const float4*)(Whh + (size_t)grow * HID) + c);
        ((__half2*)(ws + r * WH_LD + c * 4))[0] = __floats2half2_rn(v.x, v.y);
        ((__half2*)(ws + r * WH_LD + c * 4))[1] = __floats2half2_rn(v.z, v.w);
    }
    __syncthreads();

    volatile int* vd = (volatile int*)&d_done[pass];
    const int b  = tid >> 3;
    const int du = tid & 7;
    const int j  = cta * 8 + du;
    float creg = 0.0f;
    if (tid < 128) creg = c0[b * HID + j];

#pragma unroll 1
    for (int t = 0; t < S_LEN; t++) {
        float gp0 = 0.f, gp1 = 0.f, gp2 = 0.f, gp3 = 0.f;
        if (tid < 128) {
            const float* g = Gpre + (size_t)t * BATCH * G4 + b * G4 + j;
            gp0 = __ldg(g); gp1 = __ldg(g + HID); gp2 = __ldg(g + 2*HID); gp3 = __ldg(g + 3*HID);
        }
        if (t > 0) { if (tid == 0) { while (*vd < 128 * t) { } } }
        __syncthreads();

        {
            const uint4* src = (t == 0) ? (const uint4*)h0
                                        : (const uint4*)d_hbuf[(t + 1) & 1];
#pragma unroll
            for (int q = 0; q < 8; q++) {
                int i = tid + q * 256;         // 0..2047
                int r = i >> 7, c = i & 127;
                uint4 v;
                asm volatile("ld.global.cg.v4.u32 {%0,%1,%2,%3}, [%4];"
                             : "=r"(v.x), "=r"(v.y), "=r"(v.z), "=r"(v.w)
                             : "l"(src + i));
                ((uint4*)(hs + r * WH_LD))[c] = v;
            }
        }
        __syncthreads();

        {
            wmma::fragment<wmma::accumulator, 16, 16, 16, float> a0, a1;
            wmma::fill_fragment(a0, 0.0f);
            wmma::fill_fragment(a1, 0.0f);
#pragma unroll
            for (int kk = 0; kk < 128; kk += 16) {
                int k = w * 128 + kk;
                wmma::fragment<wmma::matrix_a, 16, 16, 16, __half, wmma::row_major> fa;
                wmma::fragment<wmma::matrix_b, 16, 16, 16, __half, wmma::col_major> f0, f1;
                wmma::load_matrix_sync(fa, hs + k, WH_LD);
                wmma::load_matrix_sync(f0, ws + k, WH_LD);
                wmma::load_matrix_sync(f1, ws + 16 * WH_LD + k, WH_LD);
                wmma::mma_sync(a0, fa, f0, a0);
                wmma::mma_sync(a1, fa, f1, a1);
            }
            wmma::store_matrix_sync(red + w * 576,      a0, 36, wmma::mem_row_major);
            wmma::store_matrix_sync(red + w * 576 + 16, a1, 36, wmma::mem_row_major);
        }
        __syncthreads();

        if (tid < 128) {
            float s0 = gp0, s1 = gp1, s2 = gp2, s3 = gp3;
#pragma unroll
            for (int p = 0; p < 8; p++) {
                const float* rp = red + p * 576 + b * 36;
                s0 += rp[du]; s1 += rp[8 + du]; s2 += rp[16 + du]; s3 += rp[24 + du];
            }
            float c = sigf(s1) * creg + sigf(s0) * tanhf(s2);
            float h = sigf(s3) * tanhf(c);
            creg = c;
            __half hh = __float2half_rn(h);
            d_hbuf[t & 1][b * HID + j] = hh;
            y[(size_t)t * BATCH * HID + b * HID + j] = hh;
            if (t == S_LEN - 1) { hout[b * HID + j] = h; cout[b * HID + j] = c; }
        }
        __threadfence();
        __syncthreads();
        if (tid == 0) atomicAdd(&d_done[pass], 1);
    }
}

// ---------------- dual pass v2: chains fully parallel -------------------------
// Warps 0-3: chain A matmul (K slice 256 each); warps 4-7: chain B.
// Elementwise: tid<128 chain A, tid>=128 chain B. One mm phase, one elem phase.
__global__ void __launch_bounds__(256, 1) dual_pass(
    const float* __restrict__ GpreA, const float* __restrict__ WhhA,   // enc1: G1, Whh1
    const float* __restrict__ GpreB, const float* __restrict__ WhhB,   // dec0: G0, Whh0
    const __half* __restrict__ h0B, const float* __restrict__ c0B,     // dh0H, ce0
    __half* __restrict__ yB,                                           // D0
    float* __restrict__ houtA, float* __restrict__ coutA,              // he1, ce1
    float* __restrict__ houtB, float* __restrict__ coutB)              // he0, ce0 (dump)
{
    extern __shared__ __half smp[];
    __half* wsA = smp;                          // [32][WH_LD]
    __half* wsB = smp + 32 * WH_LD;             // [32][WH_LD]
    __half* hsA = smp + 64 * WH_LD;             // [16][WH_LD]
    __half* hsB = smp + 80 * WH_LD;             // [16][WH_LD]
    float* red  = (float*)(smp + 96 * WH_LD);   // 8 x [16][36]: A in 0-3, B in 4-7
    const int tid = threadIdx.x;
    const int cta = blockIdx.x;
    const int w   = tid >> 5;

    for (int i = tid; i < 32 * 256; i += 256) {
        int r = i >> 8, c = i & 255;
        int grow = (r >> 3) * HID + cta * 8 + (r & 7);
        float4 va = __ldg((const float4*)(WhhA + (size_t)grow * HID) + c);
        ((__half2*)(wsA + r * WH_LD + c * 4))[0] = __floats2half2_rn(va.x, va.y);
        ((__half2*)(wsA + r * WH_LD + c * 4))[1] = __floats2half2_rn(va.z, va.w);
        float4 vb = __ldg((const float4*)(WhhB + (size_t)grow * HID) + c);
        ((__half2*)(wsB + r * WH_LD + c * 4))[0] = __floats2half2_rn(vb.x, vb.y);
        ((__half2*)(wsB + r * WH_LD + c * 4))[1] = __floats2half2_rn(vb.z, vb.w);
    }
    __syncthreads();

    volatile int* vd = (volatile int*)&d_done[1];
    const int lt = tid & 127;                  // lane within half-block
    const int b  = lt >> 3;
    const int du = lt & 7;
    const int j  = cta * 8 + du;
    // tid<128 owns chain A state; tid>=128 owns chain B state
    float creg = 0.0f;
    if (tid >= 128) creg = c0B[b * HID + j];

#pragma unroll 1
    for (int t = 0; t < S_LEN; t++) {
        // gate prefetch: tid<128 -> chain A gates, tid>=128 -> chain B gates
        float gp0, gp1, gp2, gp3;
        {
            const float* g = (tid < 128 ? GpreA : GpreB)
                           + (size_t)t * BATCH * G4 + b * G4 + j;
            gp0 = __ldg(g); gp1 = __ldg(g + HID); gp2 = __ldg(g + 2*HID); gp3 = __ldg(g + 3*HID);
        }
        if (t > 0) { if (tid == 0) { while (*vd < 128 * t) { } } }
        __syncthreads();

        {
            const uint4* srcA = (t == 0) ? (const uint4*)d_zerosH
                                         : (const uint4*)d_hbufA[(t + 1) & 1];
            const uint4* srcB = (t == 0) ? (const uint4*)h0B
                                         : (const uint4*)d_hbufB[(t + 1) & 1];
#pragma unroll
            for (int q = 0; q < 8; q++) {
                int i = tid + q * 256;         // 0..2047
                int r = i >> 7, c = i & 127;
                uint4 va, vb;
                asm volatile("ld.global.cg.v4.u32 {%0,%1,%2,%3}, [%4];"
                             : "=r"(va.x), "=r"(va.y), "=r"(va.z), "=r"(va.w)
                             : "l"(srcA + i));
                ((uint4*)(hsA + r * WH_LD))[c] = va;
                asm volatile("ld.global.cg.v4.u32 {%0,%1,%2,%3}, [%4];"
                             : "=r"(vb.x), "=r"(vb.y), "=r"(vb.z), "=r"(vb.w)
                             : "l"(srcB + i));
                ((uint4*)(hsB + r * WH_LD))[c] = vb;
            }
        }
        __syncthreads();

        // ONE mm phase: warps 0-3 chain A (K slice 256), warps 4-7 chain B
        {
            const __half* hs = (w < 4) ? hsA : hsB;
            const __half* ws = (w < 4) ? wsA : wsB;
            const int ks = (w & 3) * 256;
            wmma::fragment<wmma::accumulator, 16, 16, 16, float> a0, a1;
            wmma::fill_fragment(a0, 0.0f);
            wmma::fill_fragment(a1, 0.0f);
#pragma unroll
            for (int kk = 0; kk < 256; kk += 16) {
                int k = ks + kk;
                wmma::fragment<wmma::matrix_a, 16, 16, 16, __half, wmma::row_major> fa;
                wmma::fragment<wmma::matrix_b, 16, 16, 16, __half, wmma::col_major> f0, f1;
                wmma::load_matrix_sync(fa, hs + k, WH_LD);
                wmma::load_matrix_sync(f0, ws + k, WH_LD);
                wmma::load_matrix_sync(f1, ws + 16 * WH_LD + k, WH_LD);
                wmma::mma_sync(a0, fa, f0, a0);
                wmma::mma_sync(a1, fa, f1, a1);
            }
            wmma::store_matrix_sync(red + w * 576,      a0, 36, wmma::mem_row_major);
            wmma::store_matrix_sync(red + w * 576 + 16, a1, 36, wmma::mem_row_major);
        }
        __syncthreads();

        // ONE elem phase: tid<128 chain A (slots 0-3), tid>=128 chain B (slots 4-7)
        {
            const int base = (tid < 128) ? 0 : 4;
            float s0 = gp0, s1 = gp1, s2 = gp2, s3 = gp3;
#pragma unroll
            for (int p = 0; p < 4; p++) {
                const float* rp = red + (base + p) * 576 + b * 36;
                s0 += rp[du]; s1 += rp[8 + du]; s2 += rp[16 + du]; s3 += rp[24 + du];
            }
            float c = sigf(s1) * creg + sigf(s0) * tanhf(s2);
            float h = sigf(s3) * tanhf(c);
            creg = c;
            __half hh = __float2half_rn(h);
            if (tid < 128) {
                d_hbufA[t & 1][b * HID + j] = hh;
                if (t == S_LEN - 1) { houtA[b * HID + j] = h; coutA[b * HID + j] = c; }
            } else {
                d_hbufB[t & 1][b * HID + j] = hh;
                yB[(size_t)t * BATCH * HID + b * HID + j] = hh;
                if (t == S_LEN - 1) { houtB[b * HID + j] = h; coutB[b * HID + j] = c; }
            }
        }
        __threadfence();
        __syncthreads();
        if (tid == 0) atomicAdd(&d_done[1], 1);
    }
}

// ---------------- latent: dh = fp16(he @ latW^T + latb) ----------------------
__global__ void latent_kernel(const float* __restrict__ latW, const float* __restrict__ latb,
                              int which) {
    __shared__ float hesh[HID];
    int rem = blockIdx.x;          // 0..1023
    int b = rem >> 6;
    int jg = rem & 63;
    const float* he = which ? d_he1 : d_he0;
    __half* dh = which ? d_dh1H : d_dh0H;
    for (int i = threadIdx.x; i < HID; i += 256) hesh[i] = he[b * HID + i];
    __syncthreads();
    int w = threadIdx.x >> 5, lane = threadIdx.x & 31;
#pragma unroll
    for (int q = 0; q < 2; q++) {
        int j = jg * 16 + w * 2 + q;
        const float* wr = latW + (size_t)j * HID;
        float s = 0.0f;
        for (int k = lane; k < HID; k += 32) s += wr[k] * hesh[k];
#pragma unroll
        for (int o = 16; o; o >>= 1) s += __shfl_xor_sync(0xFFFFFFFFu, s, o);
        if (lane == 0) dh[b * HID + j] = __float2half_rn(s + latb[j]);
    }
}

extern "C" void kernel_launch(void* const* d_in, const int* in_sizes, int n_in,
                              void* d_out, int out_size) {
    const int*   tokens   = (const int*)  d_in[0];
    const float* emb      = (const float*)d_in[1];
    const float* dec_bias = (const float*)d_in[2];
    const float* Wih0     = (const float*)d_in[3];
    const float* Whh0     = (const float*)d_in[4];
    const float* bih0     = (const float*)d_in[5];
    const float* bhh0     = (const float*)d_in[6];
    const float* Wih1     = (const float*)d_in[7];
    const float* Whh1     = (const float*)d_in[8];
    const float* bih1     = (const float*)d_in[9];
    const float* bhh1     = (const float*)d_in[10];
    const float* latW     = (const float*)d_in[11];
    const float* latb     = (const float*)d_in[12];
    float* out = (float*)d_out;

    cudaFuncSetAttribute(gemm_h,    cudaFuncAttributeMaxDynamicSharedMemorySize, GEMM_SMEM_BYTES);
    cudaFuncSetAttribute(lstm_pass, cudaFuncAttributeMaxDynamicSharedMemorySize, PASS_SMEM_BYTES);
    cudaFuncSetAttribute(dual_pass, cudaFuncAttributeMaxDynamicSharedMemorySize, DUAL_SMEM_BYTES);

    float *pG0, *pG1, *pbc0, *pbc1, *pZF;
    float *phe0, *pce0, *phe1, *pce1;
    __half *pXH, *pY0H, *pD0H, *pD1H, *pembH, *pWH0, *pWH1;
    __half *pZH, *pdh0H, *pdh1H;
    cudaGetSymbolAddress((void**)&pG0,   d_G0);
    cudaGetSymbolAddress((void**)&pG1,   d_G1);
    cudaGetSymbolAddress((void**)&pbc0,  d_bc0);
    cudaGetSymbolAddress((void**)&pbc1,  d_bc1);
    cudaGetSymbolAddress((void**)&pZF,   d_zerosF);
    cudaGetSymbolAddress((void**)&phe0,  d_he0);
    cudaGetSymbolAddress((void**)&pce0,  d_ce0);
    cudaGetSymbolAddress((void**)&phe1,  d_he1);
    cudaGetSymbolAddress((void**)&pce1,  d_ce1);
    cudaGetSymbolAddress((void**)&pXH,   d_X);
    cudaGetSymbolAddress((void**)&pY0H,  d_Y0);
    cudaGetSymbolAddress((void**)&pD0H,  d_D0);
    cudaGetSymbolAddress((void**)&pD1H,  d_D1);
    cudaGetSymbolAddress((void**)&pembH, d_embH);
    cudaGetSymbolAddress((void**)&pWH0,  d_WH0);
    cudaGetSymbolAddress((void**)&pWH1,  d_WH1);
    cudaGetSymbolAddress((void**)&pZH,   d_zerosH);
    cudaGetSymbolAddress((void**)&pdh0H, d_dh0H);
    cudaGetSymbolAddress((void**)&pdh1H, d_dh1H);

    init_kernel<<<16, 256>>>(bih0, bhh0, bih1, bhh1);
    tohalf_kernel<<<(VOC*HID/4 + 255)/256, 256>>>(emb,  pembH, VOC*HID/4);
    tohalf_kernel<<<(G4*HID/4 + 255)/256, 256>>>(Wih0, pWH0,  G4*HID/4);
    tohalf_kernel<<<(G4*HID/4 + 255)/256, 256>>>(Wih1, pWH1,  G4*HID/4);
    embed_kernel<<<ROWS, 256>>>(tokens);

    // G0 = X @ Wih0^T + b0 (shared by enc-l0 and teacher-forced dec-l0)
    gemm_h<<<dim3(16, 16), 256, GEMM_SMEM_BYTES>>>(pXH, pWH0, pbc0, pG0, G4, HID);
    // encoder layer 0 (counter slot 0)
    lstm_pass<<<128, 256, PASS_SMEM_BYTES>>>(pG0, Whh0, pZH, pZF, pY0H, phe0, pce0, 0);
    // latent for decoder layer 0
    latent_kernel<<<1024, 256>>>(latW, latb, 0);
    // G1 = Y0 @ Wih1^T + b1
    gemm_h<<<dim3(16, 16), 256, GEMM_SMEM_BYTES>>>(pY0H, pWH1, pbc1, pG1, G4, HID);
    // enc-l1 || dec-l0 in one grid-synced kernel (counter slot 1)
    dual_pass<<<128, 256, DUAL_SMEM_BYTES>>>(pG1, Whh1, pG0, Whh0,
                                             pdh0H, pce0, pD0H,
                                             phe1, pce1, phe0, pce0);
    // latent for decoder layer 1
    latent_kernel<<<1024, 256>>>(latW, latb, 1);
    // G1d = D0 @ Wih1^T + b1
    gemm_h<<<dim3(16, 16), 256, GEMM_SMEM_BYTES>>>(pD0H, pWH1, pbc1, pG1, G4, HID);
    // decoder layer 1 (counter slot 3); hout/cout dumped into dead he0/ce0
    lstm_pass<<<128, 256, PASS_SMEM_BYTES>>>(pG1, Whh1, pdh1H, pce1, pD1H, phe0, pce0, 3);
    // logits = D1 @ embH^T + dec_bias
    gemm_h<<<dim3(16, 125), 256, GEMM_SMEM_BYTES>>>(pD1H, pembH, dec_bias, out, VOC, HID);
}